// round 9
// baseline (speedup 1.0000x reference)
#include <cuda_runtime.h>
#include <math.h>
#include <stddef.h>
#include <stdint.h>

// Problem constants
#define D_MODEL 768
#define NHEAD   12
#define HDIM    64
#define BATCH   8
#define TLEN    1024
#define SLEN    257
#define MROWS   (BATCH * TLEN)   // 8192
#define EROWS   (BATCH * SLEN)   // 2056

// ---------------- scratch (static device globals; no allocation) ------------
__device__ float g_big[(size_t)MROWS * 3072];
__device__ float g_h  [(size_t)MROWS * D_MODEL];
__device__ float g_o  [(size_t)MROWS * D_MODEL];
__device__ float g_x  [(size_t)MROWS * D_MODEL];
__device__ float g_q2 [(size_t)MROWS * D_MODEL];
__device__ float g_ekv[(size_t)EROWS * 1536];

// ---------------------------- LayerNorm (d = 768) ---------------------------
__global__ __launch_bounds__(256) void ln_kernel(
    const float* __restrict__ x, const float* __restrict__ g,
    const float* __restrict__ b, float* __restrict__ y)
{
    const int row = blockIdx.x;
    const int tid = threadIdx.x;
    const float* xr = x + (size_t)row * D_MODEL;

    float v0 = xr[tid], v1 = xr[tid + 256], v2 = xr[tid + 512];
    float s  = v0 + v1 + v2;
    float sq = v0 * v0 + v1 * v1 + v2 * v2;

    #pragma unroll
    for (int off = 16; off >= 1; off >>= 1) {
        s  += __shfl_xor_sync(0xffffffffu, s,  off);
        sq += __shfl_xor_sync(0xffffffffu, sq, off);
    }
    __shared__ float ss[8], ssq[8];
    int w = tid >> 5, l = tid & 31;
    if (l == 0) { ss[w] = s; ssq[w] = sq; }
    __syncthreads();
    float st = 0.f, sqt = 0.f;
    #pragma unroll
    for (int i = 0; i < 8; i++) { st += ss[i]; sqt += ssq[i]; }

    const float mean = st * (1.f / 768.f);
    const float var  = sqt * (1.f / 768.f) - mean * mean;
    const float rstd = rsqrtf(var + 1e-5f);

    float* yr = y + (size_t)row * D_MODEL;
    yr[tid]       = (v0 - mean) * rstd * g[tid]       + b[tid];
    yr[tid + 256] = (v1 - mean) * rstd * g[tid + 256] + b[tid + 256];
    yr[tid + 512] = (v2 - mean) * rstd * g[tid + 512] + b[tid + 512];
}

// ------------------------------ shared helpers -------------------------------
__device__ __forceinline__ float gelu_tanh(float v) {
    return 0.5f * v * (1.f + tanhf(0.7978845608028654f * (v + 0.044715f * v * v * v)));
}

__device__ __forceinline__ void mma_tf32(float c[4],
    uint32_t a0, uint32_t a1, uint32_t a2, uint32_t a3,
    uint32_t b0, uint32_t b1)
{
    asm volatile(
        "mma.sync.aligned.m16n8k8.row.col.f32.tf32.tf32.f32 "
        "{%0,%1,%2,%3}, {%4,%5,%6,%7}, {%8,%9}, {%0,%1,%2,%3};"
        : "+f"(c[0]), "+f"(c[1]), "+f"(c[2]), "+f"(c[3])
        : "r"(a0), "r"(a1), "r"(a2), "r"(a3), "r"(b0), "r"(b1));
}

__device__ __forceinline__ void cp16(uint32_t dst_smem, const float* src) {
    asm volatile("cp.async.cg.shared.global [%0], [%1], 16;"
                 :: "r"(dst_smem), "l"(src));
}

// ------------------------------ tf32 GEMM -----------------------------------
// C[M,N] = A[M,K] @ W[K,N] + bias (+resid | GELU). m16n8k8 tf32.
// CTA 128x128x32, 256 threads (8 warps, 2m x 4n), warp tile 64x32.
// Both operands cp.async, 3-stage, ONE __syncthreads per k-tile.
// A smem [128 m][36 k] (frag bank = 4g+tg), B smem [32 k][136 n] (bank 8tg+g).
#define ALD 36
#define BLD 136
#define GSTG (128 * ALD + 32 * BLD)             // 8960 floats per stage
#define GEMM_SMEM_BYTES (3 * GSTG * 4)          // 107520 B

__global__ __launch_bounds__(256, 2) void gemm_tf32_kernel(
    const float* __restrict__ A, int lda,
    const float* __restrict__ W, int ldw,
    const float* __restrict__ bias,
    const float* __restrict__ resid,
    float* __restrict__ C, int ldc,
    int M, int N, int K, int mode)   // mode: 0 plain, 1 +resid, 2 gelu
{
    extern __shared__ float sm[];
    // stage s: A at sm + s*GSTG (128x36), B at sm + s*GSTG + 128*ALD (32x136)
    const int tid = threadIdx.x, lane = tid & 31, wid = tid >> 5;
    const int wm = wid & 1, wn = wid >> 1;   // warps: 2 (m) x 4 (n)
    const int g = lane >> 2, tg = lane & 3;
    const int bm = blockIdx.y * 128, bn = blockIdx.x * 128;

    // A load: thread -> row t>>1, k-quad (t&1)*4 (4 cp16 = 16 floats)
    const int rowA = tid >> 1, qa = (tid & 1) * 4;
    int ar = bm + rowA; if (ar >= M) ar = M - 1;
    const float* aptr = A + (size_t)ar * lda;

    // B load: thread -> k-row t>>3, n-quad (t&7)*4 (4 cp16)
    const int rowB = tid >> 3, qb = (tid & 7) * 4;
    const float* bptr = W + (size_t)rowB * ldw + bn;

    const uint32_t smem0 = (uint32_t)__cvta_generic_to_shared(sm);
    const uint32_t dA0 = smem0 + (rowA * ALD) * 4;
    const uint32_t dB0 = smem0 + (128 * ALD + rowB * BLD) * 4;
    const uint32_t stS = GSTG * 4;

    float acc[4][4][4];
    #pragma unroll
    for (int mt = 0; mt < 4; mt++)
        #pragma unroll
        for (int nt = 0; nt < 4; nt++)
            #pragma unroll
            for (int e = 0; e < 4; e++) acc[mt][nt][e] = 0.f;

    const int nk = K >> 5;

    // ---- prologue: stages 0, 1 ----
    #pragma unroll
    for (int st = 0; st < 2; st++) {
        if (st < nk) {
            const float* pa = aptr + (size_t)st * 32;
            const float* pb = bptr + (size_t)st * 32 * ldw;
            const uint32_t sA = dA0 + st * stS;
            const uint32_t sB = dB0 + st * stS;
            #pragma unroll
            for (int j = 0; j < 4; j++) {
                cp16(sA + (qa + j) * 16, pa + (qa + j) * 4);
                cp16(sB + (qb + j) * 16, pb + (qb + j) * 4);
            }
        }
        asm volatile("cp.async.commit_group;");
    }

    int bufc = 0;   // kt % 3
    for (int kt = 0; kt < nk; kt++) {
        asm volatile("cp.async.wait_group 1;");   // stage kt resident
        __syncthreads();

        // issue stage kt+2 into buffer (kt+2)%3 (its readers finished at iter kt-1)
        if (kt + 2 < nk) {
            const int nb = (bufc + 2 >= 3) ? bufc - 1 : bufc + 2;
            const float* pa = aptr + (size_t)(kt + 2) * 32;
            const float* pb = bptr + (size_t)(kt + 2) * 32 * ldw;
            const uint32_t sA = dA0 + nb * stS;
            const uint32_t sB = dB0 + nb * stS;
            #pragma unroll
            for (int j = 0; j < 4; j++) {
                cp16(sA + (qa + j) * 16, pa + (qa + j) * 4);
                cp16(sB + (qb + j) * 16, pb + (qb + j) * 4);
            }
        }
        asm volatile("cp.async.commit_group;");

        const uint32_t* Au = (const uint32_t*)(sm + bufc * GSTG);
        const uint32_t* Bu = (const uint32_t*)(sm + bufc * GSTG + 128 * ALD);

        #pragma unroll
        for (int s = 0; s < 4; s++) {
            const int k0 = s * 8;
            uint32_t af[4][4], bf[4][2];
            #pragma unroll
            for (int mt = 0; mt < 4; mt++) {
                const int m0 = wm * 64 + mt * 16 + g;
                af[mt][0] = Au[(m0)     * ALD + k0 + tg];
                af[mt][1] = Au[(m0 + 8) * ALD + k0 + tg];
                af[mt][2] = Au[(m0)     * ALD + k0 + tg + 4];
                af[mt][3] = Au[(m0 + 8) * ALD + k0 + tg + 4];
            }
            #pragma unroll
            for (int nt = 0; nt < 4; nt++) {
                const int n0 = wn * 32 + nt * 8 + g;
                bf[nt][0] = Bu[(k0 + tg)     * BLD + n0];
                bf[nt][1] = Bu[(k0 + tg + 4) * BLD + n0];
            }
            #pragma unroll
            for (int mt = 0; mt < 4; mt++)
                #pragma unroll
                for (int nt = 0; nt < 4; nt++)
                    mma_tf32(acc[mt][nt], af[mt][0], af[mt][1], af[mt][2], af[mt][3],
                             bf[nt][0], bf[nt][1]);
        }
        bufc = (bufc + 1 >= 3) ? 0 : bufc + 1;
    }

    // ---- epilogue ----
    #pragma unroll
    for (int mt = 0; mt < 4; mt++) {
        const int r0 = bm + wm * 64 + mt * 16 + g;
        #pragma unroll
        for (int h2 = 0; h2 < 2; h2++) {
            const int row = r0 + 8 * h2;
            if (row >= M) continue;
            #pragma unroll
            for (int nt = 0; nt < 4; nt++) {
                const int col = bn + wn * 32 + nt * 8 + 2 * tg;
                float2 o = make_float2(acc[mt][nt][2 * h2], acc[mt][nt][2 * h2 + 1]);
                float2 bv = *(const float2*)&bias[col];
                o.x += bv.x; o.y += bv.y;
                if (mode == 1) {
                    float2 rv = *(const float2*)&resid[(size_t)row * ldc + col];
                    o.x += rv.x; o.y += rv.y;
                } else if (mode == 2) {
                    o.x = gelu_tanh(o.x); o.y = gelu_tanh(o.y);
                }
                *(float2*)&C[(size_t)row * ldc + col] = o;
            }
        }
    }
}

// ------------------- tensor-core flash attention (tf32) ----------------------
// CTA: 128 q-rows x (64-key tiles). 256 threads = 8 warps; warp w owns rows
// [16w,16w+16). S = Q K^T and O += P V both m16n8k8 tf32. P staged via SMEM.
#define QLD 68
#define KLD 68
#define VLD 72
#define PLD 68
#define ATTN_SMEM_FLOATS (128 * QLD + 64 * KLD + 64 * VLD + 128 * PLD)
#define ATTN_SMEM_BYTES (ATTN_SMEM_FLOATS * 4)   // 105472

__global__ __launch_bounds__(256, 2) void attn_tc_kernel(
    const float* __restrict__ Qp, int q_rs,
    const float* __restrict__ Kp, int k_rs,
    const float* __restrict__ Vp, int v_rs,
    float* __restrict__ Op, int o_rs,
    int Tq, int Tk, int causal)
{
    extern __shared__ float sm[];
    float* Qs = sm;                       // [128][68]
    float* Ks = Qs + 128 * QLD;           // [64][68]
    float* Vs = Ks + 64 * KLD;            // [64][72]
    float* Ps = Vs + 64 * VLD;            // [128][68]

    const int tid = threadIdx.x, lane = tid & 31, wid = tid >> 5;
    const int g = lane >> 2, tg = lane & 3;
    const int b = blockIdx.z, h = blockIdx.y;
    const int q0 = blockIdx.x * 128;
    const int rw = wid * 16;

    const float* qbase = Qp + (size_t)b * Tq * q_rs + h * HDIM;
    const float* kbase = Kp + (size_t)b * Tk * k_rs + h * HDIM;
    const float* vbase = Vp + (size_t)b * Tk * v_rs + h * HDIM;

    {
        const int r = tid >> 1, c0 = (tid & 1) * 32;
        const float* src = qbase + (size_t)(q0 + r) * q_rs + c0;
        uint32_t dst = (uint32_t)__cvta_generic_to_shared(Qs + r * QLD + c0);
        #pragma unroll
        for (int i = 0; i < 8; i++) cp16(dst + i * 16, src + 4 * i);
        asm volatile("cp.async.commit_group;");
    }

    float mrun[2] = {-1e30f, -1e30f}, lrun[2] = {0.f, 0.f};
    float o[8][4];
    #pragma unroll
    for (int nf = 0; nf < 8; nf++)
        #pragma unroll
        for (int e = 0; e < 4; e++) o[nf][e] = 0.f;

    const int ntiles = causal ? 2 * (blockIdx.x + 1) : ((Tk + 63) >> 6);
    const int kv_r = tid >> 2, kv_c = (tid & 3) * 16;

    for (int kt = 0; kt < ntiles; kt++) {
        const int k0 = kt * 64;
        __syncthreads();
        {
            int sr = k0 + kv_r; if (sr >= Tk) sr = Tk - 1;
            const float* ks = kbase + (size_t)sr * k_rs + kv_c;
            const float* vs = vbase + (size_t)sr * v_rs + kv_c;
            uint32_t dk = (uint32_t)__cvta_generic_to_shared(Ks + kv_r * KLD + kv_c);
            uint32_t dv = (uint32_t)__cvta_generic_to_shared(Vs + kv_r * VLD + kv_c);
            #pragma unroll
            for (int i = 0; i < 4; i++) cp16(dk + i * 16, ks + 4 * i);
            #pragma unroll
            for (int i = 0; i < 4; i++) cp16(dv + i * 16, vs + 4 * i);
            asm volatile("cp.async.commit_group;");
        }
        asm volatile("cp.async.wait_group 0;");
        __syncthreads();

        float sc[8][4];
        #pragma unroll
        for (int nf = 0; nf < 8; nf++)
            #pragma unroll
            for (int e = 0; e < 4; e++) sc[nf][e] = 0.f;

        const uint32_t* Qu = (const uint32_t*)Qs;
        const uint32_t* Ku = (const uint32_t*)Ks;
        #pragma unroll
        for (int ks = 0; ks < 8; ks++) {
            const int k = 8 * ks;
            uint32_t a0 = Qu[(rw + g)     * QLD + k + tg];
            uint32_t a1 = Qu[(rw + g + 8) * QLD + k + tg];
            uint32_t a2 = Qu[(rw + g)     * QLD + k + tg + 4];
            uint32_t a3 = Qu[(rw + g + 8) * QLD + k + tg + 4];
            #pragma unroll
            for (int nf = 0; nf < 8; nf++) {
                uint32_t b0 = Ku[(8 * nf + g) * KLD + k + tg];
                uint32_t b1 = Ku[(8 * nf + g) * KLD + k + tg + 4];
                mma_tf32(sc[nf], a0, a1, a2, a3, b0, b1);
            }
        }

        const int qi0 = q0 + rw + g, qi1 = qi0 + 8;
        const int cmax0 = causal ? min(qi0, Tk - 1) : (Tk - 1);
        const int cmax1 = causal ? min(qi1, Tk - 1) : (Tk - 1);
        float m0 = -1e30f, m1 = -1e30f;
        #pragma unroll
        for (int nf = 0; nf < 8; nf++) {
            const int c0i = k0 + 8 * nf + 2 * tg;
            const int c1i = c0i + 1;
            sc[nf][0] = (c0i <= cmax0) ? sc[nf][0] * 0.125f : -1e30f;
            sc[nf][1] = (c1i <= cmax0) ? sc[nf][1] * 0.125f : -1e30f;
            sc[nf][2] = (c0i <= cmax1) ? sc[nf][2] * 0.125f : -1e30f;
            sc[nf][3] = (c1i <= cmax1) ? sc[nf][3] * 0.125f : -1e30f;
            m0 = fmaxf(m0, fmaxf(sc[nf][0], sc[nf][1]));
            m1 = fmaxf(m1, fmaxf(sc[nf][2], sc[nf][3]));
        }
        #pragma unroll
        for (int off = 1; off < 4; off <<= 1) {
            m0 = fmaxf(m0, __shfl_xor_sync(0xffffffffu, m0, off));
            m1 = fmaxf(m1, __shfl_xor_sync(0xffffffffu, m1, off));
        }
        const float mn0 = fmaxf(mrun[0], m0), mn1 = fmaxf(mrun[1], m1);
        const float corr0 = __expf(mrun[0] - mn0), corr1 = __expf(mrun[1] - mn1);
        mrun[0] = mn0; mrun[1] = mn1;

        float s0 = 0.f, s1 = 0.f;
        #pragma unroll
        for (int nf = 0; nf < 8; nf++) {
            float p00 = __expf(sc[nf][0] - mn0);
            float p01 = __expf(sc[nf][1] - mn0);
            float p10 = __expf(sc[nf][2] - mn1);
            float p11 = __expf(sc[nf][3] - mn1);
            s0 += p00 + p01; s1 += p10 + p11;
            *(float2*)&Ps[(rw + g)     * PLD + 8 * nf + 2 * tg] = make_float2(p00, p01);
            *(float2*)&Ps[(rw + g + 8) * PLD + 8 * nf + 2 * tg] = make_float2(p10, p11);
            o[nf][0] *= corr0; o[nf][1] *= corr0;
            o[nf][2] *= corr1; o[nf][3] *= corr1;
        }
        #pragma unroll
        for (int off = 1; off < 4; off <<= 1) {
            s0 += __shfl_xor_sync(0xffffffffu, s0, off);
            s1 += __shfl_xor_sync(0xffffffffu, s1, off);
        }
        lrun[0] = lrun[0] * corr0 + s0;
        lrun[1] = lrun[1] * corr1 + s1;
        __syncwarp();

        const uint32_t* Pu = (const uint32_t*)Ps;
        const uint32_t* Vu = (const uint32_t*)Vs;
        #pragma unroll
        for (int ks = 0; ks < 8; ks++) {
            const int k = 8 * ks;
            uint32_t a0 = Pu[(rw + g)     * PLD + k + tg];
            uint32_t a1 = Pu[(rw + g + 8) * PLD + k + tg];
            uint32_t a2 = Pu[(rw + g)     * PLD + k + tg + 4];
            uint32_t a3 = Pu[(rw + g + 8) * PLD + k + tg + 4];
            #pragma unroll
            for (int nf = 0; nf < 8; nf++) {
                uint32_t b0 = Vu[(k + tg)     * VLD + 8 * nf + g];
                uint32_t b1 = Vu[(k + tg + 4) * VLD + 8 * nf + g];
                mma_tf32(o[nf], a0, a1, a2, a3, b0, b1);
            }
        }
    }

    const float inv0 = 1.f / lrun[0], inv1 = 1.f / lrun[1];
    const int t0 = q0 + rw + g, t1 = t0 + 8;
    float* out0 = Op + ((size_t)b * Tq + t0) * o_rs + h * HDIM;
    float* out1 = Op + ((size_t)b * Tq + t1) * o_rs + h * HDIM;
    #pragma unroll
    for (int nf = 0; nf < 8; nf++) {
        const int col = 8 * nf + 2 * tg;
        *(float2*)&out0[col] = make_float2(o[nf][0] * inv0, o[nf][1] * inv0);
        *(float2*)&out1[col] = make_float2(o[nf][2] * inv1, o[nf][3] * inv1);
    }
}

// ------------------------------- launch --------------------------------------
extern "C" void kernel_launch(void* const* d_in, const int* in_sizes, int n_in,
                              void* d_out, int out_size)
{
    const float* x            = (const float*)d_in[0];
    const float* encoder_x    = (const float*)d_in[1];
    const float* ln1_g        = (const float*)d_in[2];
    const float* ln1_b        = (const float*)d_in[3];
    const float* ln2_g        = (const float*)d_in[4];
    const float* ln2_b        = (const float*)d_in[5];
    const float* ln3_g        = (const float*)d_in[6];
    const float* ln3_b        = (const float*)d_in[7];
    const float* attn_w       = (const float*)d_in[8];
    const float* attn_b       = (const float*)d_in[9];
    const float* attn_proj_w  = (const float*)d_in[10];
    const float* attn_proj_b  = (const float*)d_in[11];
    const float* cross_w      = (const float*)d_in[12];
    const float* cross_b      = (const float*)d_in[13];
    const float* cross_proj_w = (const float*)d_in[14];
    const float* cross_proj_b = (const float*)d_in[15];
    const float* fc_w         = (const float*)d_in[16];
    const float* fc_b         = (const float*)d_in[17];
    const float* proj_w       = (const float*)d_in[18];
    const float* proj_b       = (const float*)d_in[19];

    float *big, *hbuf, *obuf, *xbuf, *q2, *ekv;
    cudaGetSymbolAddress((void**)&big,  g_big);
    cudaGetSymbolAddress((void**)&hbuf, g_h);
    cudaGetSymbolAddress((void**)&obuf, g_o);
    cudaGetSymbolAddress((void**)&xbuf, g_x);
    cudaGetSymbolAddress((void**)&q2,   g_q2);
    cudaGetSymbolAddress((void**)&ekv,  g_ekv);

    cudaFuncSetAttribute(attn_tc_kernel,
                         cudaFuncAttributeMaxDynamicSharedMemorySize,
                         ATTN_SMEM_BYTES);
    cudaFuncSetAttribute(gemm_tf32_kernel,
                         cudaFuncAttributeMaxDynamicSharedMemorySize,
                         GEMM_SMEM_BYTES);

    const int M = MROWS;        // 8192
    dim3 blk(256);
    dim3 ga(TLEN / 128, NHEAD, BATCH);   // 8 x 12 x 8

    // 1. h = LN1(x)
    ln_kernel<<<M, blk>>>(x, ln1_g, ln1_b, hbuf);
    // 2. qkv = h @ attn_w + attn_b   (8192 x 2304)
    gemm_tf32_kernel<<<dim3(2304 / 128, M / 128), blk, GEMM_SMEM_BYTES>>>(
        hbuf, 768, attn_w, 2304, attn_b, nullptr, big, 2304, M, 2304, 768, 0);
    // 3. causal self-attention
    attn_tc_kernel<<<ga, blk, ATTN_SMEM_BYTES>>>(
        big, 2304, big + 768, 2304, big + 1536, 2304, obuf, 768, TLEN, TLEN, 1);
    // 4. x1 = x + o @ attn_proj_w + attn_proj_b
    gemm_tf32_kernel<<<dim3(768 / 128, M / 128), blk, GEMM_SMEM_BYTES>>>(
        obuf, 768, attn_proj_w, 768, attn_proj_b, x, xbuf, 768, M, 768, 768, 1);
    // 5. h = LN2(x1)
    ln_kernel<<<M, blk>>>(xbuf, ln2_g, ln2_b, hbuf);
    // 6. q2 = h @ cross_w[:, :768] + cross_b[:768]
    gemm_tf32_kernel<<<dim3(768 / 128, M / 128), blk, GEMM_SMEM_BYTES>>>(
        hbuf, 768, cross_w, 2304, cross_b, nullptr, q2, 768, M, 768, 768, 0);
    // 7. ekv = encoder_x @ cross_w[:, 768:] + cross_b[768:]   (2056 x 1536)
    gemm_tf32_kernel<<<dim3(1536 / 128, (EROWS + 127) / 128), blk, GEMM_SMEM_BYTES>>>(
        encoder_x, 768, cross_w + 768, 2304, cross_b + 768, nullptr,
        ekv, 1536, EROWS, 1536, 768, 0);
    // 8. cross-attention (non-causal, Tk = 257)
    attn_tc_kernel<<<ga, blk, ATTN_SMEM_BYTES>>>(
        q2, 768, ekv, 1536, ekv + 768, 1536, obuf, 768, TLEN, SLEN, 0);
    // 9. x2 = x1 + o2 @ cross_proj_w + cross_proj_b
    gemm_tf32_kernel<<<dim3(768 / 128, M / 128), blk, GEMM_SMEM_BYTES>>>(
        obuf, 768, cross_proj_w, 768, cross_proj_b, xbuf, xbuf, 768, M, 768, 768, 1);
    // 10. h = LN3(x2)
    ln_kernel<<<M, blk>>>(xbuf, ln3_g, ln3_b, hbuf);
    // 11. fc = GELU(h @ fc_w + fc_b)  (8192 x 3072)
    gemm_tf32_kernel<<<dim3(3072 / 128, M / 128), blk, GEMM_SMEM_BYTES>>>(
        hbuf, 768, fc_w, 3072, fc_b, nullptr, big, 3072, M, 3072, 768, 2);
    // 12. out = x2 + fc @ proj_w + proj_b
    gemm_tf32_kernel<<<dim3(768 / 128, M / 128), blk, GEMM_SMEM_BYTES>>>(
        big, 3072, proj_w, 768, proj_b, xbuf, (float*)d_out, 768, M, 768, 3072, 1);
}

// round 10
// speedup vs baseline: 1.8196x; 1.8196x over previous
#include <cuda_runtime.h>
#include <cuda_fp16.h>
#include <math.h>
#include <stddef.h>
#include <stdint.h>

// Problem constants
#define D_MODEL 768
#define NHEAD   12
#define HDIM    64
#define BATCH   8
#define TLEN    1024
#define SLEN    257
#define MROWS   (BATCH * TLEN)   // 8192
#define EROWS   (BATCH * SLEN)   // 2056
#define TPADC   320              // padded cross Vt length

// ---------------- scratch (static device globals; no allocation) ------------
__device__ __half g_big[(size_t)MROWS * 3072];
__device__ __half g_h  [(size_t)MROWS * D_MODEL];
__device__ __half g_o  [(size_t)MROWS * D_MODEL];
__device__ float  g_x  [(size_t)MROWS * D_MODEL];
__device__ __half g_q2 [(size_t)MROWS * D_MODEL];
__device__ __half g_ekv[(size_t)EROWS * 1536];
__device__ __half g_enc[(size_t)EROWS * D_MODEL];
__device__ __half g_vt [(size_t)BATCH * NHEAD * HDIM * TLEN];
__device__ __half g_vtc[(size_t)BATCH * NHEAD * HDIM * TPADC];
__device__ __half g_wt [9437184];   // converted+transposed weights

// WT offsets (halfs)
#define OFF_ATTN   0          // [2304][768]
#define OFF_APROJ  1769472    // [768][768]
#define OFF_CROSS  2359296    // [2304][768]
#define OFF_CPROJ  4128768    // [768][768]
#define OFF_FC     4718592    // [3072][768]
#define OFF_PROJ   7077888    // [768][3072]

// ------------------------------ helpers --------------------------------------
__device__ __forceinline__ float gelu_tanh(float v) {
    return 0.5f * v * (1.f + tanhf(0.7978845608028654f * (v + 0.044715f * v * v * v)));
}

__device__ __forceinline__ void mma_f16(float c[4],
    uint32_t a0, uint32_t a1, uint32_t a2, uint32_t a3,
    uint32_t b0, uint32_t b1)
{
    asm volatile(
        "mma.sync.aligned.m16n8k16.row.col.f32.f16.f16.f32 "
        "{%0,%1,%2,%3}, {%4,%5,%6,%7}, {%8,%9}, {%0,%1,%2,%3};"
        : "+f"(c[0]), "+f"(c[1]), "+f"(c[2]), "+f"(c[3])
        : "r"(a0), "r"(a1), "r"(a2), "r"(a3), "r"(b0), "r"(b1));
}

__device__ __forceinline__ void cp16(uint32_t dst_smem, const void* src) {
    asm volatile("cp.async.cg.shared.global [%0], [%1], 16;"
                 :: "r"(dst_smem), "l"(src));
}

__device__ __forceinline__ uint32_t pack_h2(float a, float b) {
    __half2 h = __floats2half2_rn(a, b);
    return *reinterpret_cast<uint32_t*>(&h);
}

// ---------------------------- LayerNorm (d = 768) ---------------------------
__global__ __launch_bounds__(256) void ln_kernel(
    const float* __restrict__ x, const float* __restrict__ g,
    const float* __restrict__ b, __half* __restrict__ y)
{
    const int row = blockIdx.x;
    const int tid = threadIdx.x;
    const float* xr = x + (size_t)row * D_MODEL;

    float v0 = xr[tid], v1 = xr[tid + 256], v2 = xr[tid + 512];
    float s  = v0 + v1 + v2;
    float sq = v0 * v0 + v1 * v1 + v2 * v2;

    #pragma unroll
    for (int off = 16; off >= 1; off >>= 1) {
        s  += __shfl_xor_sync(0xffffffffu, s,  off);
        sq += __shfl_xor_sync(0xffffffffu, sq, off);
    }
    __shared__ float ss[8], ssq[8];
    int w = tid >> 5, l = tid & 31;
    if (l == 0) { ss[w] = s; ssq[w] = sq; }
    __syncthreads();
    float st = 0.f, sqt = 0.f;
    #pragma unroll
    for (int i = 0; i < 8; i++) { st += ss[i]; sqt += ssq[i]; }

    const float mean = st * (1.f / 768.f);
    const float var  = sqt * (1.f / 768.f) - mean * mean;
    const float rstd = rsqrtf(var + 1e-5f);

    __half* yr = y + (size_t)row * D_MODEL;
    yr[tid]       = __float2half_rn((v0 - mean) * rstd * g[tid]       + b[tid]);
    yr[tid + 256] = __float2half_rn((v1 - mean) * rstd * g[tid + 256] + b[tid + 256]);
    yr[tid + 512] = __float2half_rn((v2 - mean) * rstd * g[tid + 512] + b[tid + 512]);
}

// ------------------- weight convert + transpose (fp32->fp16) -----------------
// dst[n*K + k] = (half) src[k*N + n]
__global__ __launch_bounds__(256) void wconv_kernel(
    const float* __restrict__ src, __half* __restrict__ dst, int K, int N)
{
    __shared__ float t[32][33];
    const int k0 = blockIdx.y * 32, n0 = blockIdx.x * 32;
    const int tx = threadIdx.x & 31, ty = threadIdx.x >> 5;
    #pragma unroll
    for (int i = 0; i < 32; i += 8)
        t[ty + i][tx] = src[(size_t)(k0 + ty + i) * N + n0 + tx];
    __syncthreads();
    #pragma unroll
    for (int i = 0; i < 32; i += 8)
        dst[(size_t)(n0 + ty + i) * K + k0 + tx] = __float2half_rn(t[tx][ty + i]);
}

// -------------------------- encoder_x fp32 -> fp16 ---------------------------
__global__ __launch_bounds__(256) void f2h_kernel(
    const float* __restrict__ src, __half* __restrict__ dst, int n)
{
    int i = blockIdx.x * 256 + threadIdx.x;
    if (i < n) dst[i] = __float2half_rn(src[i]);
}

// ------------------------- V transpose (per b,h) ------------------------------
// dst[(bh*64 + d)*dst_rs + t] = (t < T) ? src[(b*T + t)*src_rs + off + h*64 + d] : 0
__global__ __launch_bounds__(256) void vtrans_kernel(
    const __half* __restrict__ src, __half* __restrict__ dst,
    int T, int src_rs, int dst_rs, int col_off)
{
    __shared__ __half tile[32][33];
    const int bh = blockIdx.z, b = bh / NHEAD, h = bh % NHEAD;
    const int t0 = blockIdx.x * 32, d0 = blockIdx.y * 32;
    const int tx = threadIdx.x & 31, ty = threadIdx.x >> 5;
    #pragma unroll
    for (int i = 0; i < 32; i += 8) {
        const int t = t0 + ty + i;
        __half v = __float2half(0.f);
        if (t < T) v = src[((size_t)b * T + t) * src_rs + col_off + h * HDIM + d0 + tx];
        tile[ty + i][tx] = v;
    }
    __syncthreads();
    #pragma unroll
    for (int i = 0; i < 32; i += 8)
        dst[((size_t)bh * HDIM + d0 + ty + i) * dst_rs + t0 + tx] = tile[tx][ty + i];
}

// ------------------------------ fp16 GEMM ------------------------------------
// C[M,N] = A[M,K] @ WT^T + bias (+resid | GELU). m16n8k16 fp16, fp32 acc.
// WT is [N][K] half. CTA 128x128xKT64, 256 thr (8 warps 2m x 4n), warp 64x32.
// SMEM per stage: A[128 rows][36 u32 pitch] + B[128 rows][36 u32] = 36864 B.
// Both operands cp.async; 2 stages; one __syncthreads per k-tile (R2 schedule).
#define GPITCH_B 144                     // bytes per row (36 u32)
#define GSTG_B   (256 * GPITCH_B)        // 36864
#define GEMM_SMEM_BYTES (2 * GSTG_B)     // 73728

__global__ __launch_bounds__(256, 2) void gemm_f16_kernel(
    const __half* __restrict__ A, int lda,
    const __half* __restrict__ WT, int ldb,
    const float* __restrict__ bias,
    const float* __restrict__ resid,
    void* __restrict__ Cv, int ldc,
    int M, int N, int K, int mode)   // 0: bias->half, 1: bias+resid->float, 2: bias+gelu->half
{
    extern __shared__ char smc[];
    const uint32_t smem0 = (uint32_t)__cvta_generic_to_shared(smc);
    const int tid = threadIdx.x, lane = tid & 31, wid = tid >> 5;
    const int wm = wid & 1, wn = wid >> 1;
    const int g = lane >> 2, tg = lane & 3;
    const int bm = blockIdx.y * 128, bn = blockIdx.x * 128;

    // loaders: 2 threads per row; each does 4 cp16 (64B) of the 128B row
    const int row = tid >> 1, hsel = tid & 1;
    int ar = bm + row; if (ar >= M) ar = M - 1;
    const __half* aptr = A  + (size_t)ar * lda + hsel * 32;
    const __half* bptr = WT + (size_t)(bn + row) * ldb + hsel * 32;
    const uint32_t dA = smem0 + row * GPITCH_B + hsel * 64;
    const uint32_t dB = smem0 + 128 * GPITCH_B + row * GPITCH_B + hsel * 64;

    float acc[4][4][4];
    #pragma unroll
    for (int mt = 0; mt < 4; mt++)
        #pragma unroll
        for (int nt = 0; nt < 4; nt++)
            #pragma unroll
            for (int e = 0; e < 4; e++) acc[mt][nt][e] = 0.f;

    const int nk = K >> 6;   // K/64

    // prologue: stage 0
    #pragma unroll
    for (int j = 0; j < 4; j++) {
        cp16(dA + j * 16, aptr + j * 8);
        cp16(dB + j * 16, bptr + j * 8);
    }
    asm volatile("cp.async.commit_group;");

    for (int kt = 0; kt < nk; kt++) {
        asm volatile("cp.async.wait_group 0;");
        __syncthreads();

        if (kt + 1 < nk) {
            const int st = (kt + 1) & 1;
            const __half* pa = aptr + (size_t)(kt + 1) * 64;
            const __half* pb = bptr + (size_t)(kt + 1) * 64;
            const uint32_t oA = dA + st * GSTG_B;
            const uint32_t oB = dB + st * GSTG_B;
            #pragma unroll
            for (int j = 0; j < 4; j++) {
                cp16(oA + j * 16, pa + j * 8);
                cp16(oB + j * 16, pb + j * 8);
            }
            asm volatile("cp.async.commit_group;");
        }

        const uint32_t* Au = (const uint32_t*)(smc + (kt & 1) * GSTG_B);
        const uint32_t* Bu = (const uint32_t*)(smc + (kt & 1) * GSTG_B + 128 * GPITCH_B);

        #pragma unroll
        for (int ks = 0; ks < 4; ks++) {
            const int ko = 8 * ks;
            uint32_t af[4][4], bf[4][2];
            #pragma unroll
            for (int mt = 0; mt < 4; mt++) {
                const int m0 = wm * 64 + mt * 16 + g;
                af[mt][0] = Au[(m0)     * 36 + ko + tg];
                af[mt][1] = Au[(m0 + 8) * 36 + ko + tg];
                af[mt][2] = Au[(m0)     * 36 + ko + tg + 4];
                af[mt][3] = Au[(m0 + 8) * 36 + ko + tg + 4];
            }
            #pragma unroll
            for (int nt = 0; nt < 4; nt++) {
                const int n0 = wn * 32 + nt * 8 + g;
                bf[nt][0] = Bu[n0 * 36 + ko + tg];
                bf[nt][1] = Bu[n0 * 36 + ko + tg + 4];
            }
            #pragma unroll
            for (int mt = 0; mt < 4; mt++)
                #pragma unroll
                for (int nt = 0; nt < 4; nt++)
                    mma_f16(acc[mt][nt], af[mt][0], af[mt][1], af[mt][2], af[mt][3],
                            bf[nt][0], bf[nt][1]);
        }
    }

    // ---- epilogue ----
    #pragma unroll
    for (int mt = 0; mt < 4; mt++) {
        const int r0 = bm + wm * 64 + mt * 16 + g;
        #pragma unroll
        for (int h2 = 0; h2 < 2; h2++) {
            const int rr = r0 + 8 * h2;
            if (rr >= M) continue;
            #pragma unroll
            for (int nt = 0; nt < 4; nt++) {
                const int col = bn + wn * 32 + nt * 8 + 2 * tg;
                float ox = acc[mt][nt][2 * h2]     ;
                float oy = acc[mt][nt][2 * h2 + 1] ;
                float2 bv = *(const float2*)&bias[col];
                ox += bv.x; oy += bv.y;
                if (mode == 1) {
                    float2 rv = *(const float2*)&resid[(size_t)rr * ldc + col];
                    ox += rv.x; oy += rv.y;
                    *(float2*)&((float*)Cv)[(size_t)rr * ldc + col] = make_float2(ox, oy);
                } else {
                    if (mode == 2) { ox = gelu_tanh(ox); oy = gelu_tanh(oy); }
                    __half2 hv = __floats2half2_rn(ox, oy);
                    *(__half2*)&((__half*)Cv)[(size_t)rr * ldc + col] = hv;
                }
            }
        }
    }
}

// ------------------- fp16 tensor-core flash attention -------------------------
// CTA: 128 q-rows x 64-key tiles, 256 thr = 8 warps, warp w owns rows [16w,16w+16).
// S = Q K^T and O += P V^T via m16n8k16 fp16 (Vt pre-transposed in gmem).
// SMEM (bytes): Q[128][144], K[64][144], Vt[64][144], P[128][144].
#define APITCH 144
#define AQ_OFF  0
#define AK_OFF  (128 * APITCH)                 // 18432
#define AV_OFF  (AK_OFF + 64 * APITCH)         // 27648
#define AP_OFF  (AV_OFF + 64 * APITCH)         // 36864
#define ATTN_SMEM_BYTES (AP_OFF + 128 * APITCH) // 55296

__global__ __launch_bounds__(256, 2) void attn_f16_kernel(
    const __half* __restrict__ Qp, int q_rs,
    const __half* __restrict__ Kp, int k_rs,
    const __half* __restrict__ Vt, int vt_rs,   // [BH*64][vt_rs], rows = d
    __half* __restrict__ Op, int o_rs,
    int Tq, int Tk, int causal)
{
    extern __shared__ char smc[];
    const uint32_t smem0 = (uint32_t)__cvta_generic_to_shared(smc);
    const uint32_t* Q32 = (const uint32_t*)(smc + AQ_OFF);
    const uint32_t* K32 = (const uint32_t*)(smc + AK_OFF);
    const uint32_t* V32 = (const uint32_t*)(smc + AV_OFF);
    uint32_t*       P32 = (uint32_t*)(smc + AP_OFF);

    const int tid = threadIdx.x, lane = tid & 31, wid = tid >> 5;
    const int g = lane >> 2, tg = lane & 3;
    const int b = blockIdx.z, h = blockIdx.y;
    const int q0 = blockIdx.x * 128;
    const int rw = wid * 16;

    const __half* qbase = Qp + (size_t)b * Tq * q_rs + h * HDIM;
    const __half* kbase = Kp + (size_t)b * Tk * k_rs + h * HDIM;
    const __half* vbase = Vt + ((size_t)(b * NHEAD + h) * HDIM) * vt_rs;

    // load Q tile (128 x 64 half)
    {
        const int r = tid >> 1, hs = tid & 1;
        const __half* src = qbase + (size_t)(q0 + r) * q_rs + hs * 32;
        const uint32_t dst = smem0 + AQ_OFF + r * APITCH + hs * 64;
        #pragma unroll
        for (int j = 0; j < 4; j++) cp16(dst + j * 16, src + j * 8);
        asm volatile("cp.async.commit_group;");
    }

    float mrun[2] = {-1e30f, -1e30f}, lrun[2] = {0.f, 0.f};
    float o[8][4];
    #pragma unroll
    for (int nf = 0; nf < 8; nf++)
        #pragma unroll
        for (int e = 0; e < 4; e++) o[nf][e] = 0.f;

    const int ntiles = causal ? 2 * (blockIdx.x + 1) : ((Tk + 63) >> 6);
    const int kv_r = tid >> 2;              // 0..63
    const int kv_c = (tid & 3) * 16;        // half offset, 2 chunks of 16B

    for (int kt = 0; kt < ntiles; kt++) {
        const int k0 = kt * 64;
        __syncthreads();
        {
            int sr = k0 + kv_r; if (sr >= Tk) sr = Tk - 1;
            const __half* ks = kbase + (size_t)sr * k_rs + kv_c;
            const __half* vs = vbase + (size_t)kv_r * vt_rs + k0 + kv_c;
            const uint32_t dk = smem0 + AK_OFF + kv_r * APITCH + (tid & 3) * 32;
            const uint32_t dv = smem0 + AV_OFF + kv_r * APITCH + (tid & 3) * 32;
            cp16(dk, ks);      cp16(dk + 16, ks + 8);
            cp16(dv, vs);      cp16(dv + 16, vs + 8);
            asm volatile("cp.async.commit_group;");
        }
        asm volatile("cp.async.wait_group 0;");
        __syncthreads();

        // ---- S = Q K^T ----
        float sc[8][4];
        #pragma unroll
        for (int nf = 0; nf < 8; nf++)
            #pragma unroll
            for (int e = 0; e < 4; e++) sc[nf][e] = 0.f;

        #pragma unroll
        for (int ks = 0; ks < 4; ks++) {
            const int ko = 8 * ks;
            uint32_t a0 = Q32[(rw + g)     * 36 + ko + tg];
            uint32_t a1 = Q32[(rw + g + 8) * 36 + ko + tg];
            uint32_t a2 = Q32[(rw + g)     * 36 + ko + tg + 4];
            uint32_t a3 = Q32[(rw + g + 8) * 36 + ko + tg + 4];
            #pragma unroll
            for (int nf = 0; nf < 8; nf++) {
                uint32_t b0 = K32[(8 * nf + g) * 36 + ko + tg];
                uint32_t b1 = K32[(8 * nf + g) * 36 + ko + tg + 4];
                mma_f16(sc[nf], a0, a1, a2, a3, b0, b1);
            }
        }

        // ---- scale + mask + online softmax ----
        const int qi0 = q0 + rw + g, qi1 = qi0 + 8;
        const int cmax0 = causal ? min(qi0, Tk - 1) : (Tk - 1);
        const int cmax1 = causal ? min(qi1, Tk - 1) : (Tk - 1);
        float m0 = -1e30f, m1 = -1e30f;
        #pragma unroll
        for (int nf = 0; nf < 8; nf++) {
            const int c0i = k0 + 8 * nf + 2 * tg;
            const int c1i = c0i + 1;
            sc[nf][0] = (c0i <= cmax0) ? sc[nf][0] * 0.125f : -1e30f;
            sc[nf][1] = (c1i <= cmax0) ? sc[nf][1] * 0.125f : -1e30f;
            sc[nf][2] = (c0i <= cmax1) ? sc[nf][2] * 0.125f : -1e30f;
            sc[nf][3] = (c1i <= cmax1) ? sc[nf][3] * 0.125f : -1e30f;
            m0 = fmaxf(m0, fmaxf(sc[nf][0], sc[nf][1]));
            m1 = fmaxf(m1, fmaxf(sc[nf][2], sc[nf][3]));
        }
        #pragma unroll
        for (int off = 1; off < 4; off <<= 1) {
            m0 = fmaxf(m0, __shfl_xor_sync(0xffffffffu, m0, off));
            m1 = fmaxf(m1, __shfl_xor_sync(0xffffffffu, m1, off));
        }
        const float mn0 = fmaxf(mrun[0], m0), mn1 = fmaxf(mrun[1], m1);
        const float corr0 = __expf(mrun[0] - mn0), corr1 = __expf(mrun[1] - mn1);
        mrun[0] = mn0; mrun[1] = mn1;

        float s0 = 0.f, s1 = 0.f;
        #pragma unroll
        for (int nf = 0; nf < 8; nf++) {
            float p00 = __expf(sc[nf][0] - mn0);
            float p01 = __expf(sc[nf][1] - mn0);
            float p10 = __expf(sc[nf][2] - mn1);
            float p11 = __expf(sc[nf][3] - mn1);
            s0 += p00 + p01; s1 += p10 + p11;
            P32[(rw + g)     * 36 + 4 * nf + tg] = pack_h2(p00, p01);
            P32[(rw + g + 8) * 36 + 4 * nf + tg] = pack_h2(p10, p11);
            o[nf][0] *= corr0; o[nf][1] *= corr0;
            o[nf][2] *= corr1; o[nf][3] *= corr1;
        }
        #pragma unroll
        for (int off = 1; off < 4; off <<= 1) {
            s0 += __shfl_xor_sync(0xffffffffu, s0, off);
            s1 += __shfl_xor_sync(0xffffffffu, s1, off);
        }
        lrun[0] = lrun[0] * corr0 + s0;
        lrun[1] = lrun[1] * corr1 + s1;
        __syncwarp();

        // ---- O += P V^T ----
        #pragma unroll
        for (int ks = 0; ks < 4; ks++) {
            const int ko = 8 * ks;
            uint32_t a0 = P32[(rw + g)     * 36 + ko + tg];
            uint32_t a1 = P32[(rw + g + 8) * 36 + ko + tg];
            uint32_t a2 = P32[(rw + g)     * 36 + ko + tg + 4];
            uint32_t a3 = P32[(rw + g + 8) * 36 + ko + tg + 4];
            #pragma unroll
            for (int nf = 0; nf < 8; nf++) {
                uint32_t b0 = V32[(8 * nf + g) * 36 + ko + tg];
                uint32_t b1 = V32[(8 * nf + g) * 36 + ko + tg + 4];
                mma_f16(o[nf], a0, a1, a2, a3, b0, b1);
            }
        }
    }

    const float inv0 = 1.f / lrun[0], inv1 = 1.f / lrun[1];
    const int t0 = q0 + rw + g, t1 = t0 + 8;
    __half* out0 = Op + ((size_t)b * Tq + t0) * o_rs + h * HDIM;
    __half* out1 = Op + ((size_t)b * Tq + t1) * o_rs + h * HDIM;
    #pragma unroll
    for (int nf = 0; nf < 8; nf++) {
        const int col = 8 * nf + 2 * tg;
        *(__half2*)&out0[col] = __floats2half2_rn(o[nf][0] * inv0, o[nf][1] * inv0);
        *(__half2*)&out1[col] = __floats2half2_rn(o[nf][2] * inv1, o[nf][3] * inv1);
    }
}

// ------------------------------- launch --------------------------------------
extern "C" void kernel_launch(void* const* d_in, const int* in_sizes, int n_in,
                              void* d_out, int out_size)
{
    const float* x            = (const float*)d_in[0];
    const float* encoder_x    = (const float*)d_in[1];
    const float* ln1_g        = (const float*)d_in[2];
    const float* ln1_b        = (const float*)d_in[3];
    const float* ln2_g        = (const float*)d_in[4];
    const float* ln2_b        = (const float*)d_in[5];
    const float* ln3_g        = (const float*)d_in[6];
    const float* ln3_b        = (const float*)d_in[7];
    const float* attn_w       = (const float*)d_in[8];
    const float* attn_b       = (const float*)d_in[9];
    const float* attn_proj_w  = (const float*)d_in[10];
    const float* attn_proj_b  = (const float*)d_in[11];
    const float* cross_w      = (const float*)d_in[12];
    const float* cross_b      = (const float*)d_in[13];
    const float* cross_proj_w = (const float*)d_in[14];
    const float* cross_proj_b = (const float*)d_in[15];
    const float* fc_w         = (const float*)d_in[16];
    const float* fc_b         = (const float*)d_in[17];
    const float* proj_w       = (const float*)d_in[18];
    const float* proj_b       = (const float*)d_in[19];

    __half *big, *hbuf, *obuf, *q2, *ekv, *enc, *vt, *vtc, *wt;
    float  *xbuf;
    cudaGetSymbolAddress((void**)&big,  g_big);
    cudaGetSymbolAddress((void**)&hbuf, g_h);
    cudaGetSymbolAddress((void**)&obuf, g_o);
    cudaGetSymbolAddress((void**)&xbuf, g_x);
    cudaGetSymbolAddress((void**)&q2,   g_q2);
    cudaGetSymbolAddress((void**)&ekv,  g_ekv);
    cudaGetSymbolAddress((void**)&enc,  g_enc);
    cudaGetSymbolAddress((void**)&vt,   g_vt);
    cudaGetSymbolAddress((void**)&vtc,  g_vtc);
    cudaGetSymbolAddress((void**)&wt,   g_wt);

    cudaFuncSetAttribute(attn_f16_kernel,
                         cudaFuncAttributeMaxDynamicSharedMemorySize,
                         ATTN_SMEM_BYTES);
    cudaFuncSetAttribute(gemm_f16_kernel,
                         cudaFuncAttributeMaxDynamicSharedMemorySize,
                         GEMM_SMEM_BYTES);

    const int M = MROWS;        // 8192
    dim3 blk(256);
    dim3 ga(TLEN / 128, NHEAD, BATCH);   // 8 x 12 x 8

    // 0a. convert+transpose all weights (fp32 [K][N] -> fp16 [N][K])
    wconv_kernel<<<dim3(2304/32, 768/32),  blk>>>(attn_w,       wt + OFF_ATTN,  768, 2304);
    wconv_kernel<<<dim3(768/32,  768/32),  blk>>>(attn_proj_w,  wt + OFF_APROJ, 768, 768);
    wconv_kernel<<<dim3(2304/32, 768/32),  blk>>>(cross_w,      wt + OFF_CROSS, 768, 2304);
    wconv_kernel<<<dim3(768/32,  768/32),  blk>>>(cross_proj_w, wt + OFF_CPROJ, 768, 768);
    wconv_kernel<<<dim3(3072/32, 768/32),  blk>>>(fc_w,         wt + OFF_FC,    768, 3072);
    wconv_kernel<<<dim3(768/32,  3072/32), blk>>>(proj_w,       wt + OFF_PROJ,  3072, 768);
    // 0b. encoder_x -> half
    f2h_kernel<<<(EROWS * D_MODEL + 255) / 256, blk>>>(encoder_x, enc, EROWS * D_MODEL);

    // 1. h = LN1(x)
    ln_kernel<<<M, blk>>>(x, ln1_g, ln1_b, hbuf);
    // 2. qkv = h @ attn_w + attn_b  (8192 x 2304, half out)
    gemm_f16_kernel<<<dim3(2304/128, M/128), blk, GEMM_SMEM_BYTES>>>(
        hbuf, 768, wt + OFF_ATTN, 768, attn_b, nullptr, big, 2304, M, 2304, 768, 0);
    // 2b. transpose self V -> vt [bh][d][t]
    vtrans_kernel<<<dim3(TLEN/32, HDIM/32, BATCH*NHEAD), blk>>>(
        big, vt, TLEN, 2304, TLEN, 1536);
    // 3. causal self-attention
    attn_f16_kernel<<<ga, blk, ATTN_SMEM_BYTES>>>(
        big, 2304, big + 768, 2304, vt, TLEN, obuf, 768, TLEN, TLEN, 1);
    // 4. x1 = x + o @ attn_proj_w + attn_proj_b  (float out)
    gemm_f16_kernel<<<dim3(768/128, M/128), blk, GEMM_SMEM_BYTES>>>(
        obuf, 768, wt + OFF_APROJ, 768, attn_proj_b, x, xbuf, 768, M, 768, 768, 1);
    // 5. h = LN2(x1)
    ln_kernel<<<M, blk>>>(xbuf, ln2_g, ln2_b, hbuf);
    // 6. q2 = h @ cross_w[:, :768] + cross_b[:768]  (half out)
    gemm_f16_kernel<<<dim3(768/128, M/128), blk, GEMM_SMEM_BYTES>>>(
        hbuf, 768, wt + OFF_CROSS, 768, cross_b, nullptr, q2, 768, M, 768, 768, 0);
    // 7. ekv = encoder_x @ cross_w[:, 768:] + cross_b[768:]  (2056 x 1536, half)
    gemm_f16_kernel<<<dim3(1536/128, (EROWS + 127)/128), blk, GEMM_SMEM_BYTES>>>(
        enc, 768, wt + OFF_CROSS + 768 * 768, 768, cross_b + 768, nullptr,
        ekv, 1536, EROWS, 1536, 768, 0);
    // 7b. transpose cross V -> vtc [bh][d][t_pad] (zero-padded to 320)
    vtrans_kernel<<<dim3(TPADC/32, HDIM/32, BATCH*NHEAD), blk>>>(
        ekv, vtc, SLEN, 1536, TPADC, 768);
    // 8. cross-attention (non-causal, Tk = 257)
    attn_f16_kernel<<<ga, blk, ATTN_SMEM_BYTES>>>(
        q2, 768, ekv, 1536, vtc, TPADC, obuf, 768, TLEN, SLEN, 0);
    // 9. x2 = x1 + o2 @ cross_proj_w + cross_proj_b  (float out, in-place resid)
    gemm_f16_kernel<<<dim3(768/128, M/128), blk, GEMM_SMEM_BYTES>>>(
        obuf, 768, wt + OFF_CPROJ, 768, cross_proj_b, xbuf, xbuf, 768, M, 768, 768, 1);
    // 10. h = LN3(x2)
    ln_kernel<<<M, blk>>>(xbuf, ln3_g, ln3_b, hbuf);
    // 11. fc = GELU(h @ fc_w + fc_b)  (8192 x 3072, half out)
    gemm_f16_kernel<<<dim3(3072/128, M/128), blk, GEMM_SMEM_BYTES>>>(
        hbuf, 768, wt + OFF_FC, 768, fc_b, nullptr, big, 3072, M, 3072, 768, 2);
    // 12. out = x2 + fc @ proj_w + proj_b  (float out)
    gemm_f16_kernel<<<dim3(768/128, M/128), blk, GEMM_SMEM_BYTES>>>(
        big, 3072, wt + OFF_PROJ, 3072, proj_b, xbuf, (float*)d_out, 768, M, 768, 3072, 1);
}

// round 11
// speedup vs baseline: 1.8994x; 1.0438x over previous
#include <cuda_runtime.h>
#include <cuda_fp16.h>
#include <math.h>
#include <stddef.h>
#include <stdint.h>

// Problem constants
#define D_MODEL 768
#define NHEAD   12
#define HDIM    64
#define BATCH   8
#define TLEN    1024
#define SLEN    257
#define MROWS   (BATCH * TLEN)   // 8192
#define EROWS   (BATCH * SLEN)   // 2056
#define TPADC   320              // padded cross Vt length

// ---------------- scratch (static device globals; no allocation) ------------
__device__ __half g_big[(size_t)MROWS * 3072];
__device__ __half g_h  [(size_t)MROWS * D_MODEL];
__device__ __half g_o  [(size_t)MROWS * D_MODEL];
__device__ float  g_x  [(size_t)MROWS * D_MODEL];
__device__ __half g_q2 [(size_t)MROWS * D_MODEL];
__device__ __half g_ekv[(size_t)EROWS * 1536];
__device__ __half g_enc[(size_t)EROWS * D_MODEL];
__device__ __half g_vt [(size_t)BATCH * NHEAD * HDIM * TLEN];
__device__ __half g_vtc[(size_t)BATCH * NHEAD * HDIM * TPADC];
__device__ __half g_wt [9437184];   // converted+transposed weights

// WT offsets (halfs)
#define OFF_ATTN   0          // [2304][768]
#define OFF_APROJ  1769472    // [768][768]
#define OFF_CROSS  2359296    // [2304][768]
#define OFF_CPROJ  4128768    // [768][768]
#define OFF_FC     4718592    // [3072][768]
#define OFF_PROJ   7077888    // [768][3072]

// ------------------------------ helpers --------------------------------------
__device__ __forceinline__ float gelu_tanh(float v) {
    return 0.5f * v * (1.f + tanhf(0.7978845608028654f * (v + 0.044715f * v * v * v)));
}

__device__ __forceinline__ void mma_f16(float c[4],
    uint32_t a0, uint32_t a1, uint32_t a2, uint32_t a3,
    uint32_t b0, uint32_t b1)
{
    asm volatile(
        "mma.sync.aligned.m16n8k16.row.col.f32.f16.f16.f32 "
        "{%0,%1,%2,%3}, {%4,%5,%6,%7}, {%8,%9}, {%0,%1,%2,%3};"
        : "+f"(c[0]), "+f"(c[1]), "+f"(c[2]), "+f"(c[3])
        : "r"(a0), "r"(a1), "r"(a2), "r"(a3), "r"(b0), "r"(b1));
}

__device__ __forceinline__ void cp16(uint32_t dst_smem, const void* src) {
    asm volatile("cp.async.cg.shared.global [%0], [%1], 16;"
                 :: "r"(dst_smem), "l"(src));
}

__device__ __forceinline__ void ldsm_x4(
    uint32_t& r0, uint32_t& r1, uint32_t& r2, uint32_t& r3, uint32_t addr)
{
    asm volatile("ldmatrix.sync.aligned.m8n8.x4.shared.b16 {%0,%1,%2,%3}, [%4];"
                 : "=r"(r0), "=r"(r1), "=r"(r2), "=r"(r3) : "r"(addr));
}

__device__ __forceinline__ uint32_t pack_h2(float a, float b) {
    __half2 h = __floats2half2_rn(a, b);
    return *reinterpret_cast<uint32_t*>(&h);
}

// ---------------------------- LayerNorm (d = 768) ---------------------------
__global__ __launch_bounds__(256) void ln_kernel(
    const float* __restrict__ x, const float* __restrict__ g,
    const float* __restrict__ b, __half* __restrict__ y)
{
    const int row = blockIdx.x;
    const int tid = threadIdx.x;
    const float* xr = x + (size_t)row * D_MODEL;

    float v0 = xr[tid], v1 = xr[tid + 256], v2 = xr[tid + 512];
    float s  = v0 + v1 + v2;
    float sq = v0 * v0 + v1 * v1 + v2 * v2;

    #pragma unroll
    for (int off = 16; off >= 1; off >>= 1) {
        s  += __shfl_xor_sync(0xffffffffu, s,  off);
        sq += __shfl_xor_sync(0xffffffffu, sq, off);
    }
    __shared__ float ss[8], ssq[8];
    int w = tid >> 5, l = tid & 31;
    if (l == 0) { ss[w] = s; ssq[w] = sq; }
    __syncthreads();
    float st = 0.f, sqt = 0.f;
    #pragma unroll
    for (int i = 0; i < 8; i++) { st += ss[i]; sqt += ssq[i]; }

    const float mean = st * (1.f / 768.f);
    const float var  = sqt * (1.f / 768.f) - mean * mean;
    const float rstd = rsqrtf(var + 1e-5f);

    __half* yr = y + (size_t)row * D_MODEL;
    yr[tid]       = __float2half_rn((v0 - mean) * rstd * g[tid]       + b[tid]);
    yr[tid + 256] = __float2half_rn((v1 - mean) * rstd * g[tid + 256] + b[tid + 256]);
    yr[tid + 512] = __float2half_rn((v2 - mean) * rstd * g[tid + 512] + b[tid + 512]);
}

// ------------------- weight convert + transpose (fp32->fp16) -----------------
__global__ __launch_bounds__(256) void wconv_kernel(
    const float* __restrict__ src, __half* __restrict__ dst, int K, int N)
{
    __shared__ float t[32][33];
    const int k0 = blockIdx.y * 32, n0 = blockIdx.x * 32;
    const int tx = threadIdx.x & 31, ty = threadIdx.x >> 5;
    #pragma unroll
    for (int i = 0; i < 32; i += 8)
        t[ty + i][tx] = src[(size_t)(k0 + ty + i) * N + n0 + tx];
    __syncthreads();
    #pragma unroll
    for (int i = 0; i < 32; i += 8)
        dst[(size_t)(n0 + ty + i) * K + k0 + tx] = __float2half_rn(t[tx][ty + i]);
}

// -------------------------- encoder_x fp32 -> fp16 ---------------------------
__global__ __launch_bounds__(256) void f2h_kernel(
    const float* __restrict__ src, __half* __restrict__ dst, int n)
{
    int i = blockIdx.x * 256 + threadIdx.x;
    if (i < n) dst[i] = __float2half_rn(src[i]);
}

// ------------------------- V transpose (per b,h) ------------------------------
__global__ __launch_bounds__(256) void vtrans_kernel(
    const __half* __restrict__ src, __half* __restrict__ dst,
    int T, int src_rs, int dst_rs, int col_off)
{
    __shared__ __half tile[32][33];
    const int bh = blockIdx.z, b = bh / NHEAD, h = bh % NHEAD;
    const int t0 = blockIdx.x * 32, d0 = blockIdx.y * 32;
    const int tx = threadIdx.x & 31, ty = threadIdx.x >> 5;
    #pragma unroll
    for (int i = 0; i < 32; i += 8) {
        const int t = t0 + ty + i;
        __half v = __float2half(0.f);
        if (t < T) v = src[((size_t)b * T + t) * src_rs + col_off + h * HDIM + d0 + tx];
        tile[ty + i][tx] = v;
    }
    __syncthreads();
    #pragma unroll
    for (int i = 0; i < 32; i += 8)
        dst[((size_t)bh * HDIM + d0 + ty + i) * dst_rs + t0 + tx] = tile[tx][ty + i];
}

// ------------------------------ fp16 GEMM ------------------------------------
// C[M,N] = A[M,K] @ WT^T + bias (+resid | GELU). m16n8k16 fp16, fp32 acc.
// WT is [N][K] half. CTA 128x128xKT64, 256 thr (8 warps 2m x 4n), warp 64x32.
// Fragments via ldmatrix.x4 (pitch 144B -> conflict-free).
#define GPITCH_B 144                     // bytes per row (36 u32)
#define GSTG_B   (256 * GPITCH_B)        // 36864
#define GEMM_SMEM_BYTES (2 * GSTG_B)     // 73728

__global__ __launch_bounds__(256, 2) void gemm_f16_kernel(
    const __half* __restrict__ A, int lda,
    const __half* __restrict__ WT, int ldb,
    const float* __restrict__ bias,
    const float* __restrict__ resid,
    void* __restrict__ Cv, int ldc,
    int M, int N, int K, int mode)   // 0: bias->half, 1: bias+resid->float, 2: bias+gelu->half
{
    extern __shared__ char smc[];
    const uint32_t smem0 = (uint32_t)__cvta_generic_to_shared(smc);
    const int tid = threadIdx.x, lane = tid & 31, wid = tid >> 5;
    const int wm = wid & 1, wn = wid >> 1;
    const int g = lane >> 2, tg = lane & 3;
    const int bm = blockIdx.y * 128, bn = blockIdx.x * 128;

    // loaders: 2 threads per row; each does 4 cp16 (64B) of the 128B row
    const int row = tid >> 1, hsel = tid & 1;
    int ar = bm + row; if (ar >= M) ar = M - 1;
    const __half* aptr = A  + (size_t)ar * lda + hsel * 32;
    const __half* bptr = WT + (size_t)(bn + row) * ldb + hsel * 32;
    const uint32_t dA = smem0 + row * GPITCH_B + hsel * 64;
    const uint32_t dB = smem0 + 128 * GPITCH_B + row * GPITCH_B + hsel * 64;

    // ldmatrix base addresses
    const uint32_t aLm = smem0 + (wm * 64 + (lane & 15)) * GPITCH_B + (lane >> 4) * 16;
    const uint32_t bLm = smem0 + 128 * GPITCH_B
        + (wn * 32 + (lane & 7) + ((lane >> 4) << 3)) * GPITCH_B
        + ((lane >> 3) & 1) * 16;

    float acc[4][4][4];
    #pragma unroll
    for (int mt = 0; mt < 4; mt++)
        #pragma unroll
        for (int nt = 0; nt < 4; nt++)
            #pragma unroll
            for (int e = 0; e < 4; e++) acc[mt][nt][e] = 0.f;

    const int nk = K >> 6;   // K/64

    // prologue: stage 0
    #pragma unroll
    for (int j = 0; j < 4; j++) {
        cp16(dA + j * 16, aptr + j * 8);
        cp16(dB + j * 16, bptr + j * 8);
    }
    asm volatile("cp.async.commit_group;");

    for (int kt = 0; kt < nk; kt++) {
        asm volatile("cp.async.wait_group 0;");
        __syncthreads();

        if (kt + 1 < nk) {
            const int st = (kt + 1) & 1;
            const __half* pa = aptr + (size_t)(kt + 1) * 64;
            const __half* pb = bptr + (size_t)(kt + 1) * 64;
            const uint32_t oA = dA + st * GSTG_B;
            const uint32_t oB = dB + st * GSTG_B;
            #pragma unroll
            for (int j = 0; j < 4; j++) {
                cp16(oA + j * 16, pa + j * 8);
                cp16(oB + j * 16, pb + j * 8);
            }
            asm volatile("cp.async.commit_group;");
        }

        const uint32_t so = (kt & 1) * GSTG_B;

        #pragma unroll
        for (int ks = 0; ks < 4; ks++) {
            uint32_t af[4][4], bf[4][2];
            #pragma unroll
            for (int mt = 0; mt < 4; mt++)
                ldsm_x4(af[mt][0], af[mt][1], af[mt][2], af[mt][3],
                        aLm + so + mt * (16 * GPITCH_B) + ks * 32);
            #pragma unroll
            for (int p = 0; p < 2; p++) {
                uint32_t r0, r1, r2, r3;
                ldsm_x4(r0, r1, r2, r3, bLm + so + p * (16 * GPITCH_B) + ks * 32);
                bf[2 * p][0] = r0;     bf[2 * p][1] = r1;
                bf[2 * p + 1][0] = r2; bf[2 * p + 1][1] = r3;
            }
            #pragma unroll
            for (int mt = 0; mt < 4; mt++)
                #pragma unroll
                for (int nt = 0; nt < 4; nt++)
                    mma_f16(acc[mt][nt], af[mt][0], af[mt][1], af[mt][2], af[mt][3],
                            bf[nt][0], bf[nt][1]);
        }
    }

    // ---- epilogue ----
    #pragma unroll
    for (int mt = 0; mt < 4; mt++) {
        const int r0 = bm + wm * 64 + mt * 16 + g;
        #pragma unroll
        for (int h2 = 0; h2 < 2; h2++) {
            const int rr = r0 + 8 * h2;
            if (rr >= M) continue;
            #pragma unroll
            for (int nt = 0; nt < 4; nt++) {
                const int col = bn + wn * 32 + nt * 8 + 2 * tg;
                float ox = acc[mt][nt][2 * h2];
                float oy = acc[mt][nt][2 * h2 + 1];
                float2 bv = *(const float2*)&bias[col];
                ox += bv.x; oy += bv.y;
                if (mode == 1) {
                    float2 rv = *(const float2*)&resid[(size_t)rr * ldc + col];
                    ox += rv.x; oy += rv.y;
                    *(float2*)&((float*)Cv)[(size_t)rr * ldc + col] = make_float2(ox, oy);
                } else {
                    if (mode == 2) { ox = gelu_tanh(ox); oy = gelu_tanh(oy); }
                    __half2 hv = __floats2half2_rn(ox, oy);
                    *(__half2*)&((__half*)Cv)[(size_t)rr * ldc + col] = hv;
                }
            }
        }
    }
}

// ------------------- fp16 tensor-core flash attention -------------------------
// CTA: 128 q-rows x 64-key tiles, 256 thr = 8 warps, warp w owns rows [16w,16w+16).
// S = Q K^T and O += P V^T via m16n8k16 fp16. Fragments via ldmatrix.x4.
#define APITCH 144
#define AQ_OFF  0
#define AK_OFF  (128 * APITCH)
#define AV_OFF  (AK_OFF + 64 * APITCH)
#define AP_OFF  (AV_OFF + 64 * APITCH)
#define ATTN_SMEM_BYTES (AP_OFF + 128 * APITCH)   // 55296

__global__ __launch_bounds__(256, 2) void attn_f16_kernel(
    const __half* __restrict__ Qp, int q_rs,
    const __half* __restrict__ Kp, int k_rs,
    const __half* __restrict__ Vt, int vt_rs,
    __half* __restrict__ Op, int o_rs,
    int Tq, int Tk, int causal)
{
    extern __shared__ char smc[];
    const uint32_t smem0 = (uint32_t)__cvta_generic_to_shared(smc);
    uint32_t* P32 = (uint32_t*)(smc + AP_OFF);

    const int tid = threadIdx.x, lane = tid & 31, wid = tid >> 5;
    const int g = lane >> 2, tg = lane & 3;
    const int b = blockIdx.z, h = blockIdx.y;
    const int q0 = blockIdx.x * 128;
    const int rw = wid * 16;

    const __half* qbase = Qp + (size_t)b * Tq * q_rs + h * HDIM;
    const __half* kbase = Kp + (size_t)b * Tk * k_rs + h * HDIM;
    const __half* vbase = Vt + ((size_t)(b * NHEAD + h) * HDIM) * vt_rs;

    // ldmatrix bases
    const uint32_t lmRow16 = (lane & 15) * APITCH + (lane >> 4) * 16;   // A-style
    const uint32_t lmRowB  = ((lane & 7) + ((lane >> 4) << 3)) * APITCH
                           + ((lane >> 3) & 1) * 16;                    // B-style
    const uint32_t qLm = smem0 + AQ_OFF + rw * APITCH + lmRow16;
    const uint32_t kLm = smem0 + AK_OFF + lmRowB;
    const uint32_t vLm = smem0 + AV_OFF + lmRowB;
    const uint32_t pLm = smem0 + AP_OFF + rw * APITCH + lmRow16;

    // load Q tile (128 x 64 half)
    {
        const int r = tid >> 1, hs = tid & 1;
        const __half* src = qbase + (size_t)(q0 + r) * q_rs + hs * 32;
        const uint32_t dst = smem0 + AQ_OFF + r * APITCH + hs * 64;
        #pragma unroll
        for (int j = 0; j < 4; j++) cp16(dst + j * 16, src + j * 8);
        asm volatile("cp.async.commit_group;");
    }

    float mrun[2] = {-1e30f, -1e30f}, lrun[2] = {0.f, 0.f};
    float o[8][4];
    #pragma unroll
    for (int nf = 0; nf < 8; nf++)
        #pragma unroll
        for (int e = 0; e < 4; e++) o[nf][e] = 0.f;

    const int ntiles = causal ? 2 * (blockIdx.x + 1) : ((Tk + 63) >> 6);
    const int kv_r = tid >> 2;
    const int kv_c = (tid & 3) * 16;

    for (int kt = 0; kt < ntiles; kt++) {
        const int k0 = kt * 64;
        __syncthreads();
        {
            int sr = k0 + kv_r; if (sr >= Tk) sr = Tk - 1;
            const __half* ks = kbase + (size_t)sr * k_rs + kv_c;
            const __half* vs = vbase + (size_t)kv_r * vt_rs + k0 + kv_c;
            const uint32_t dk = smem0 + AK_OFF + kv_r * APITCH + (tid & 3) * 32;
            const uint32_t dv = smem0 + AV_OFF + kv_r * APITCH + (tid & 3) * 32;
            cp16(dk, ks);      cp16(dk + 16, ks + 8);
            cp16(dv, vs);      cp16(dv + 16, vs + 8);
            asm volatile("cp.async.commit_group;");
        }
        asm volatile("cp.async.wait_group 0;");
        __syncthreads();

        // ---- S = Q K^T ----
        float sc[8][4];
        #pragma unroll
        for (int nf = 0; nf < 8; nf++)
            #pragma unroll
            for (int e = 0; e < 4; e++) sc[nf][e] = 0.f;

        #pragma unroll
        for (int ks = 0; ks < 4; ks++) {
            uint32_t a0, a1, a2, a3;
            ldsm_x4(a0, a1, a2, a3, qLm + ks * 32);
            #pragma unroll
            for (int p = 0; p < 4; p++) {
                uint32_t b00, b01, b10, b11;
                ldsm_x4(b00, b01, b10, b11, kLm + p * (16 * APITCH) + ks * 32);
                mma_f16(sc[2 * p],     a0, a1, a2, a3, b00, b01);
                mma_f16(sc[2 * p + 1], a0, a1, a2, a3, b10, b11);
            }
        }

        // ---- scale + mask + online softmax ----
        const int qi0 = q0 + rw + g, qi1 = qi0 + 8;
        const int cmax0 = causal ? min(qi0, Tk - 1) : (Tk - 1);
        const int cmax1 = causal ? min(qi1, Tk - 1) : (Tk - 1);
        float m0 = -1e30f, m1 = -1e30f;
        #pragma unroll
        for (int nf = 0; nf < 8; nf++) {
            const int c0i = k0 + 8 * nf + 2 * tg;
            const int c1i = c0i + 1;
            sc[nf][0] = (c0i <= cmax0) ? sc[nf][0] * 0.125f : -1e30f;
            sc[nf][1] = (c1i <= cmax0) ? sc[nf][1] * 0.125f : -1e30f;
            sc[nf][2] = (c0i <= cmax1) ? sc[nf][2] * 0.125f : -1e30f;
            sc[nf][3] = (c1i <= cmax1) ? sc[nf][3] * 0.125f : -1e30f;
            m0 = fmaxf(m0, fmaxf(sc[nf][0], sc[nf][1]));
            m1 = fmaxf(m1, fmaxf(sc[nf][2], sc[nf][3]));
        }
        #pragma unroll
        for (int off = 1; off < 4; off <<= 1) {
            m0 = fmaxf(m0, __shfl_xor_sync(0xffffffffu, m0, off));
            m1 = fmaxf(m1, __shfl_xor_sync(0xffffffffu, m1, off));
        }
        const float mn0 = fmaxf(mrun[0], m0), mn1 = fmaxf(mrun[1], m1);
        const float corr0 = __expf(mrun[0] - mn0), corr1 = __expf(mrun[1] - mn1);
        mrun[0] = mn0; mrun[1] = mn1;

        float s0 = 0.f, s1 = 0.f;
        #pragma unroll
        for (int nf = 0; nf < 8; nf++) {
            float p00 = __expf(sc[nf][0] - mn0);
            float p01 = __expf(sc[nf][1] - mn0);
            float p10 = __expf(sc[nf][2] - mn1);
            float p11 = __expf(sc[nf][3] - mn1);
            s0 += p00 + p01; s1 += p10 + p11;
            P32[(rw + g)     * 36 + 4 * nf + tg] = pack_h2(p00, p01);
            P32[(rw + g + 8) * 36 + 4 * nf + tg] = pack_h2(p10, p11);
            o[nf][0] *= corr0; o[nf][1] *= corr0;
            o[nf][2] *= corr1; o[nf][3] *= corr1;
        }
        #pragma unroll
        for (int off = 1; off < 4; off <<= 1) {
            s0 += __shfl_xor_sync(0xffffffffu, s0, off);
            s1 += __shfl_xor_sync(0xffffffffu, s1, off);
        }
        lrun[0] = lrun[0] * corr0 + s0;
        lrun[1] = lrun[1] * corr1 + s1;
        __syncwarp();

        // ---- O += P V^T ----
        #pragma unroll
        for (int ks = 0; ks < 4; ks++) {
            uint32_t a0, a1, a2, a3;
            ldsm_x4(a0, a1, a2, a3, pLm + ks * 32);
            #pragma unroll
            for (int p = 0; p < 4; p++) {
                uint32_t b00, b01, b10, b11;
                ldsm_x4(b00, b01, b10, b11, vLm + p * (16 * APITCH) + ks * 32);
                mma_f16(o[2 * p],     a0, a1, a2, a3, b00, b01);
                mma_f16(o[2 * p + 1], a0, a1, a2, a3, b10, b11);
            }
        }
    }

    const float inv0 = 1.f / lrun[0], inv1 = 1.f / lrun[1];
    const int t0 = q0 + rw + g, t1 = t0 + 8;
    __half* out0 = Op + ((size_t)b * Tq + t0) * o_rs + h * HDIM;
    __half* out1 = Op + ((size_t)b * Tq + t1) * o_rs + h * HDIM;
    #pragma unroll
    for (int nf = 0; nf < 8; nf++) {
        const int col = 8 * nf + 2 * tg;
        *(__half2*)&out0[col] = __floats2half2_rn(o[nf][0] * inv0, o[nf][1] * inv0);
        *(__half2*)&out1[col] = __floats2half2_rn(o[nf][2] * inv1, o[nf][3] * inv1);
    }
}

// ------------------------------- launch --------------------------------------
extern "C" void kernel_launch(void* const* d_in, const int* in_sizes, int n_in,
                              void* d_out, int out_size)
{
    const float* x            = (const float*)d_in[0];
    const float* encoder_x    = (const float*)d_in[1];
    const float* ln1_g        = (const float*)d_in[2];
    const float* ln1_b        = (const float*)d_in[3];
    const float* ln2_g        = (const float*)d_in[4];
    const float* ln2_b        = (const float*)d_in[5];
    const float* ln3_g        = (const float*)d_in[6];
    const float* ln3_b        = (const float*)d_in[7];
    const float* attn_w       = (const float*)d_in[8];
    const float* attn_b       = (const float*)d_in[9];
    const float* attn_proj_w  = (const float*)d_in[10];
    const float* attn_proj_b  = (const float*)d_in[11];
    const float* cross_w      = (const float*)d_in[12];
    const float* cross_b      = (const float*)d_in[13];
    const float* cross_proj_w = (const float*)d_in[14];
    const float* cross_proj_b = (const float*)d_in[15];
    const float* fc_w         = (const float*)d_in[16];
    const float* fc_b         = (const float*)d_in[17];
    const float* proj_w       = (const float*)d_in[18];
    const float* proj_b       = (const float*)d_in[19];

    __half *big, *hbuf, *obuf, *q2, *ekv, *enc, *vt, *vtc, *wt;
    float  *xbuf;
    cudaGetSymbolAddress((void**)&big,  g_big);
    cudaGetSymbolAddress((void**)&hbuf, g_h);
    cudaGetSymbolAddress((void**)&obuf, g_o);
    cudaGetSymbolAddress((void**)&xbuf, g_x);
    cudaGetSymbolAddress((void**)&q2,   g_q2);
    cudaGetSymbolAddress((void**)&ekv,  g_ekv);
    cudaGetSymbolAddress((void**)&enc,  g_enc);
    cudaGetSymbolAddress((void**)&vt,   g_vt);
    cudaGetSymbolAddress((void**)&vtc,  g_vtc);
    cudaGetSymbolAddress((void**)&wt,   g_wt);

    cudaFuncSetAttribute(attn_f16_kernel,
                         cudaFuncAttributeMaxDynamicSharedMemorySize,
                         ATTN_SMEM_BYTES);
    cudaFuncSetAttribute(gemm_f16_kernel,
                         cudaFuncAttributeMaxDynamicSharedMemorySize,
                         GEMM_SMEM_BYTES);

    const int M = MROWS;        // 8192
    dim3 blk(256);
    dim3 ga(TLEN / 128, NHEAD, BATCH);   // 8 x 12 x 8

    // 0a. convert+transpose all weights (fp32 [K][N] -> fp16 [N][K])
    wconv_kernel<<<dim3(2304/32, 768/32),  blk>>>(attn_w,       wt + OFF_ATTN,  768, 2304);
    wconv_kernel<<<dim3(768/32,  768/32),  blk>>>(attn_proj_w,  wt + OFF_APROJ, 768, 768);
    wconv_kernel<<<dim3(2304/32, 768/32),  blk>>>(cross_w,      wt + OFF_CROSS, 768, 2304);
    wconv_kernel<<<dim3(768/32,  768/32),  blk>>>(cross_proj_w, wt + OFF_CPROJ, 768, 768);
    wconv_kernel<<<dim3(3072/32, 768/32),  blk>>>(fc_w,         wt + OFF_FC,    768, 3072);
    wconv_kernel<<<dim3(768/32,  3072/32), blk>>>(proj_w,       wt + OFF_PROJ,  3072, 768);
    // 0b. encoder_x -> half
    f2h_kernel<<<(EROWS * D_MODEL + 255) / 256, blk>>>(encoder_x, enc, EROWS * D_MODEL);

    // 1. h = LN1(x)
    ln_kernel<<<M, blk>>>(x, ln1_g, ln1_b, hbuf);
    // 2. qkv = h @ attn_w + attn_b  (8192 x 2304, half out)
    gemm_f16_kernel<<<dim3(2304/128, M/128), blk, GEMM_SMEM_BYTES>>>(
        hbuf, 768, wt + OFF_ATTN, 768, attn_b, nullptr, big, 2304, M, 2304, 768, 0);
    // 2b. transpose self V -> vt [bh][d][t]
    vtrans_kernel<<<dim3(TLEN/32, HDIM/32, BATCH*NHEAD), blk>>>(
        big, vt, TLEN, 2304, TLEN, 1536);
    // 3. causal self-attention
    attn_f16_kernel<<<ga, blk, ATTN_SMEM_BYTES>>>(
        big, 2304, big + 768, 2304, vt, TLEN, obuf, 768, TLEN, TLEN, 1);
    // 4. x1 = x + o @ attn_proj_w + attn_proj_b  (float out)
    gemm_f16_kernel<<<dim3(768/128, M/128), blk, GEMM_SMEM_BYTES>>>(
        obuf, 768, wt + OFF_APROJ, 768, attn_proj_b, x, xbuf, 768, M, 768, 768, 1);
    // 5. h = LN2(x1)
    ln_kernel<<<M, blk>>>(xbuf, ln2_g, ln2_b, hbuf);
    // 6. q2 = h @ cross_w[:, :768] + cross_b[:768]  (half out)
    gemm_f16_kernel<<<dim3(768/128, M/128), blk, GEMM_SMEM_BYTES>>>(
        hbuf, 768, wt + OFF_CROSS, 768, cross_b, nullptr, q2, 768, M, 768, 768, 0);
    // 7. ekv = encoder_x @ cross_w[:, 768:] + cross_b[768:]  (2056 x 1536, half)
    gemm_f16_kernel<<<dim3(1536/128, (EROWS + 127)/128), blk, GEMM_SMEM_BYTES>>>(
        enc, 768, wt + OFF_CROSS + 768 * 768, 768, cross_b + 768, nullptr,
        ekv, 1536, EROWS, 1536, 768, 0);
    // 7b. transpose cross V -> vtc [bh][d][t_pad] (zero-padded to 320)
    vtrans_kernel<<<dim3(TPADC/32, HDIM/32, BATCH*NHEAD), blk>>>(
        ekv, vtc, SLEN, 1536, TPADC, 768);
    // 8. cross-attention (non-causal, Tk = 257)
    attn_f16_kernel<<<ga, blk, ATTN_SMEM_BYTES>>>(
        q2, 768, ekv, 1536, vtc, TPADC, obuf, 768, TLEN, SLEN, 0);
    // 9. x2 = x1 + o2 @ cross_proj_w + cross_proj_b  (float out, in-place resid)
    gemm_f16_kernel<<<dim3(768/128, M/128), blk, GEMM_SMEM_BYTES>>>(
        obuf, 768, wt + OFF_CPROJ, 768, cross_proj_b, xbuf, xbuf, 768, M, 768, 768, 1);
    // 10. h = LN3(x2)
    ln_kernel<<<M, blk>>>(xbuf, ln3_g, ln3_b, hbuf);
    // 11. fc = GELU(h @ fc_w + fc_b)  (8192 x 3072, half out)
    gemm_f16_kernel<<<dim3(3072/128, M/128), blk, GEMM_SMEM_BYTES>>>(
        hbuf, 768, wt + OFF_FC, 768, fc_b, nullptr, big, 3072, M, 3072, 768, 2);
    // 12. out = x2 + fc @ proj_w + proj_b  (float out)
    gemm_f16_kernel<<<dim3(768/128, M/128), blk, GEMM_SMEM_BYTES>>>(
        big, 3072, wt + OFF_PROJ, 3072, proj_b, xbuf, (float*)d_out, 768, M, 768, 3072, 1);
}

// round 12
// speedup vs baseline: 1.9300x; 1.0161x over previous
#include <cuda_runtime.h>
#include <cuda_fp16.h>
#include <math.h>
#include <stddef.h>
#include <stdint.h>

// Problem constants
#define D_MODEL 768
#define NHEAD   12
#define HDIM    64
#define BATCH   8
#define TLEN    1024
#define SLEN    257
#define MROWS   (BATCH * TLEN)   // 8192
#define EROWS   (BATCH * SLEN)   // 2056
#define TPADC   320              // padded cross Vt length

// ---------------- scratch (static device globals; no allocation) ------------
__device__ __half g_big[(size_t)MROWS * 3072];
__device__ __half g_h  [(size_t)MROWS * D_MODEL];
__device__ __half g_o  [(size_t)MROWS * D_MODEL];
__device__ float  g_x  [(size_t)MROWS * D_MODEL];
__device__ __half g_q2 [(size_t)MROWS * D_MODEL];
__device__ __half g_ekv[(size_t)EROWS * 1536];
__device__ __half g_enc[(size_t)EROWS * D_MODEL];
__device__ __half g_vt [(size_t)BATCH * NHEAD * HDIM * TLEN];
__device__ __half g_vtc[(size_t)BATCH * NHEAD * HDIM * TPADC];
__device__ __half g_wt [9437184];   // converted+transposed weights

// WT offsets (halfs)
#define OFF_ATTN   0          // [2304][768]
#define OFF_APROJ  1769472    // [768][768]
#define OFF_CROSS  2359296    // [2304][768]
#define OFF_CPROJ  4128768    // [768][768]
#define OFF_FC     4718592    // [3072][768]
#define OFF_PROJ   7077888    // [768][3072]

// ------------------------------ helpers --------------------------------------
__device__ __forceinline__ float gelu_tanh(float v) {
    return 0.5f * v * (1.f + tanhf(0.7978845608028654f * (v + 0.044715f * v * v * v)));
}

__device__ __forceinline__ void mma_f16(float c[4],
    uint32_t a0, uint32_t a1, uint32_t a2, uint32_t a3,
    uint32_t b0, uint32_t b1)
{
    asm volatile(
        "mma.sync.aligned.m16n8k16.row.col.f32.f16.f16.f32 "
        "{%0,%1,%2,%3}, {%4,%5,%6,%7}, {%8,%9}, {%0,%1,%2,%3};"
        : "+f"(c[0]), "+f"(c[1]), "+f"(c[2]), "+f"(c[3])
        : "r"(a0), "r"(a1), "r"(a2), "r"(a3), "r"(b0), "r"(b1));
}

__device__ __forceinline__ void cp16(uint32_t dst_smem, const void* src) {
    asm volatile("cp.async.cg.shared.global [%0], [%1], 16;"
                 :: "r"(dst_smem), "l"(src));
}

__device__ __forceinline__ void ldsm_x4(
    uint32_t& r0, uint32_t& r1, uint32_t& r2, uint32_t& r3, uint32_t addr)
{
    asm volatile("ldmatrix.sync.aligned.m8n8.x4.shared.b16 {%0,%1,%2,%3}, [%4];"
                 : "=r"(r0), "=r"(r1), "=r"(r2), "=r"(r3) : "r"(addr));
}

__device__ __forceinline__ uint32_t pack_h2(float a, float b) {
    __half2 h = __floats2half2_rn(a, b);
    return *reinterpret_cast<uint32_t*>(&h);
}

// ---------------------------- LayerNorm (d = 768) ---------------------------
__global__ __launch_bounds__(256) void ln_kernel(
    const float* __restrict__ x, const float* __restrict__ g,
    const float* __restrict__ b, __half* __restrict__ y)
{
    const int row = blockIdx.x;
    const int tid = threadIdx.x;
    const float* xr = x + (size_t)row * D_MODEL;

    float v0 = xr[tid], v1 = xr[tid + 256], v2 = xr[tid + 512];
    float s  = v0 + v1 + v2;
    float sq = v0 * v0 + v1 * v1 + v2 * v2;

    #pragma unroll
    for (int off = 16; off >= 1; off >>= 1) {
        s  += __shfl_xor_sync(0xffffffffu, s,  off);
        sq += __shfl_xor_sync(0xffffffffu, sq, off);
    }
    __shared__ float ss[8], ssq[8];
    int w = tid >> 5, l = tid & 31;
    if (l == 0) { ss[w] = s; ssq[w] = sq; }
    __syncthreads();
    float st = 0.f, sqt = 0.f;
    #pragma unroll
    for (int i = 0; i < 8; i++) { st += ss[i]; sqt += ssq[i]; }

    const float mean = st * (1.f / 768.f);
    const float var  = sqt * (1.f / 768.f) - mean * mean;
    const float rstd = rsqrtf(var + 1e-5f);

    __half* yr = y + (size_t)row * D_MODEL;
    yr[tid]       = __float2half_rn((v0 - mean) * rstd * g[tid]       + b[tid]);
    yr[tid + 256] = __float2half_rn((v1 - mean) * rstd * g[tid + 256] + b[tid + 256]);
    yr[tid + 512] = __float2half_rn((v2 - mean) * rstd * g[tid + 512] + b[tid + 512]);
}

// ------------------- weight convert + transpose (fp32->fp16) -----------------
__global__ __launch_bounds__(256) void wconv_kernel(
    const float* __restrict__ src, __half* __restrict__ dst, int K, int N)
{
    __shared__ float t[32][33];
    const int k0 = blockIdx.y * 32, n0 = blockIdx.x * 32;
    const int tx = threadIdx.x & 31, ty = threadIdx.x >> 5;
    #pragma unroll
    for (int i = 0; i < 32; i += 8)
        t[ty + i][tx] = src[(size_t)(k0 + ty + i) * N + n0 + tx];
    __syncthreads();
    #pragma unroll
    for (int i = 0; i < 32; i += 8)
        dst[(size_t)(n0 + ty + i) * K + k0 + tx] = __float2half_rn(t[tx][ty + i]);
}

// -------------------------- encoder_x fp32 -> fp16 ---------------------------
__global__ __launch_bounds__(256) void f2h_kernel(
    const float* __restrict__ src, __half* __restrict__ dst, int n)
{
    int i = blockIdx.x * 256 + threadIdx.x;
    if (i < n) dst[i] = __float2half_rn(src[i]);
}

// ------------------------- V transpose (per b,h) ------------------------------
__global__ __launch_bounds__(256) void vtrans_kernel(
    const __half* __restrict__ src, __half* __restrict__ dst,
    int T, int src_rs, int dst_rs, int col_off)
{
    __shared__ __half tile[32][33];
    const int bh = blockIdx.z, b = bh / NHEAD, h = bh % NHEAD;
    const int t0 = blockIdx.x * 32, d0 = blockIdx.y * 32;
    const int tx = threadIdx.x & 31, ty = threadIdx.x >> 5;
    #pragma unroll
    for (int i = 0; i < 32; i += 8) {
        const int t = t0 + ty + i;
        __half v = __float2half(0.f);
        if (t < T) v = src[((size_t)b * T + t) * src_rs + col_off + h * HDIM + d0 + tx];
        tile[ty + i][tx] = v;
    }
    __syncthreads();
    #pragma unroll
    for (int i = 0; i < 32; i += 8)
        dst[((size_t)bh * HDIM + d0 + ty + i) * dst_rs + t0 + tx] = tile[tx][ty + i];
}

// ------------------------------ fp16 GEMM ------------------------------------
// C[M,N] = A[M,K] @ WT^T + bias (+resid | GELU). m16n8k16 fp16, fp32 acc.
// WT is [N][K] half. CTA 128x128xKT64, 256 thr (8 warps 2m x 4n), warp 64x32.
// Fragments via ldmatrix.x4 (pitch 144B -> conflict-free).
#define GPITCH_B 144                     // bytes per row (36 u32)
#define GSTG_B   (256 * GPITCH_B)        // 36864
#define GEMM_SMEM_BYTES (2 * GSTG_B)     // 73728

__global__ __launch_bounds__(256, 2) void gemm_f16_kernel(
    const __half* __restrict__ A, int lda,
    const __half* __restrict__ WT, int ldb,
    const float* __restrict__ bias,
    const float* __restrict__ resid,
    void* __restrict__ Cv, int ldc,
    int M, int N, int K, int mode)   // 0: bias->half, 1: bias+resid->float, 2: bias+gelu->half
{
    extern __shared__ char smc[];
    const uint32_t smem0 = (uint32_t)__cvta_generic_to_shared(smc);
    const int tid = threadIdx.x, lane = tid & 31, wid = tid >> 5;
    const int wm = wid & 1, wn = wid >> 1;
    const int g = lane >> 2, tg = lane & 3;
    const int bm = blockIdx.y * 128, bn = blockIdx.x * 128;

    const int row = tid >> 1, hsel = tid & 1;
    int ar = bm + row; if (ar >= M) ar = M - 1;
    const __half* aptr = A  + (size_t)ar * lda + hsel * 32;
    const __half* bptr = WT + (size_t)(bn + row) * ldb + hsel * 32;
    const uint32_t dA = smem0 + row * GPITCH_B + hsel * 64;
    const uint32_t dB = smem0 + 128 * GPITCH_B + row * GPITCH_B + hsel * 64;

    const uint32_t aLm = smem0 + (wm * 64 + (lane & 15)) * GPITCH_B + (lane >> 4) * 16;
    const uint32_t bLm = smem0 + 128 * GPITCH_B
        + (wn * 32 + (lane & 7) + ((lane >> 4) << 3)) * GPITCH_B
        + ((lane >> 3) & 1) * 16;

    float acc[4][4][4];
    #pragma unroll
    for (int mt = 0; mt < 4; mt++)
        #pragma unroll
        for (int nt = 0; nt < 4; nt++)
            #pragma unroll
            for (int e = 0; e < 4; e++) acc[mt][nt][e] = 0.f;

    const int nk = K >> 6;   // K/64

    #pragma unroll
    for (int j = 0; j < 4; j++) {
        cp16(dA + j * 16, aptr + j * 8);
        cp16(dB + j * 16, bptr + j * 8);
    }
    asm volatile("cp.async.commit_group;");

    for (int kt = 0; kt < nk; kt++) {
        asm volatile("cp.async.wait_group 0;");
        __syncthreads();

        if (kt + 1 < nk) {
            const int st = (kt + 1) & 1;
            const __half* pa = aptr + (size_t)(kt + 1) * 64;
            const __half* pb = bptr + (size_t)(kt + 1) * 64;
            const uint32_t oA = dA + st * GSTG_B;
            const uint32_t oB = dB + st * GSTG_B;
            #pragma unroll
            for (int j = 0; j < 4; j++) {
                cp16(oA + j * 16, pa + j * 8);
                cp16(oB + j * 16, pb + j * 8);
            }
            asm volatile("cp.async.commit_group;");
        }

        const uint32_t so = (kt & 1) * GSTG_B;

        #pragma unroll
        for (int ks = 0; ks < 4; ks++) {
            uint32_t af[4][4], bf[4][2];
            #pragma unroll
            for (int mt = 0; mt < 4; mt++)
                ldsm_x4(af[mt][0], af[mt][1], af[mt][2], af[mt][3],
                        aLm + so + mt * (16 * GPITCH_B) + ks * 32);
            #pragma unroll
            for (int p = 0; p < 2; p++) {
                uint32_t r0, r1, r2, r3;
                ldsm_x4(r0, r1, r2, r3, bLm + so + p * (16 * GPITCH_B) + ks * 32);
                bf[2 * p][0] = r0;     bf[2 * p][1] = r1;
                bf[2 * p + 1][0] = r2; bf[2 * p + 1][1] = r3;
            }
            #pragma unroll
            for (int mt = 0; mt < 4; mt++)
                #pragma unroll
                for (int nt = 0; nt < 4; nt++)
                    mma_f16(acc[mt][nt], af[mt][0], af[mt][1], af[mt][2], af[mt][3],
                            bf[nt][0], bf[nt][1]);
        }
    }

    // ---- epilogue ----
    #pragma unroll
    for (int mt = 0; mt < 4; mt++) {
        const int r0 = bm + wm * 64 + mt * 16 + g;
        #pragma unroll
        for (int h2 = 0; h2 < 2; h2++) {
            const int rr = r0 + 8 * h2;
            if (rr >= M) continue;
            #pragma unroll
            for (int nt = 0; nt < 4; nt++) {
                const int col = bn + wn * 32 + nt * 8 + 2 * tg;
                float ox = acc[mt][nt][2 * h2];
                float oy = acc[mt][nt][2 * h2 + 1];
                float2 bv = *(const float2*)&bias[col];
                ox += bv.x; oy += bv.y;
                if (mode == 1) {
                    float2 rv = *(const float2*)&resid[(size_t)rr * ldc + col];
                    ox += rv.x; oy += rv.y;
                    *(float2*)&((float*)Cv)[(size_t)rr * ldc + col] = make_float2(ox, oy);
                } else {
                    if (mode == 2) { ox = gelu_tanh(ox); oy = gelu_tanh(oy); }
                    __half2 hv = __floats2half2_rn(ox, oy);
                    *(__half2*)&((__half*)Cv)[(size_t)rr * ldc + col] = hv;
                }
            }
        }
    }
}

// ------------------- fp16 tensor-core flash attention -------------------------
// CTA: 128 q-rows x 64-key tiles, 256 thr = 8 warps, warp w owns rows [16w,16w+16).
// K/V tiles double-buffered (cp.async prefetch of tile kt+1 overlaps compute of kt);
// ONE __syncthreads per tile. Fragments via ldmatrix.x4, pitch 144B.
#define APITCH 144
#define AQ_OFF  0
#define AKSTG   (64 * APITCH)                       // 9216 per K/V buffer
#define AK_OFF  (128 * APITCH)                      // 18432
#define AV_OFF  (AK_OFF + 2 * AKSTG)                // 36864
#define AP_OFF  (AV_OFF + 2 * AKSTG)                // 55296
#define ATTN_SMEM_BYTES (AP_OFF + 128 * APITCH)     // 73728

__global__ __launch_bounds__(256, 2) void attn_f16_kernel(
    const __half* __restrict__ Qp, int q_rs,
    const __half* __restrict__ Kp, int k_rs,
    const __half* __restrict__ Vt, int vt_rs,
    __half* __restrict__ Op, int o_rs,
    int Tq, int Tk, int causal)
{
    extern __shared__ char smc[];
    const uint32_t smem0 = (uint32_t)__cvta_generic_to_shared(smc);
    uint32_t* P32 = (uint32_t*)(smc + AP_OFF);

    const int tid = threadIdx.x, lane = tid & 31, wid = tid >> 5;
    const int g = lane >> 2, tg = lane & 3;
    const int b = blockIdx.z, h = blockIdx.y;
    const int q0 = blockIdx.x * 128;
    const int rw = wid * 16;

    const __half* qbase = Qp + (size_t)b * Tq * q_rs + h * HDIM;
    const __half* kbase = Kp + (size_t)b * Tk * k_rs + h * HDIM;
    const __half* vbase = Vt + ((size_t)(b * NHEAD + h) * HDIM) * vt_rs;

    // ldmatrix bases
    const uint32_t lmRow16 = (lane & 15) * APITCH + (lane >> 4) * 16;   // A-style
    const uint32_t lmRowB  = ((lane & 7) + ((lane >> 4) << 3)) * APITCH
                           + ((lane >> 3) & 1) * 16;                    // B-style
    const uint32_t qLm = smem0 + AQ_OFF + rw * APITCH + lmRow16;
    const uint32_t kLm = smem0 + AK_OFF + lmRowB;
    const uint32_t vLm = smem0 + AV_OFF + lmRowB;
    const uint32_t pLm = smem0 + AP_OFF + rw * APITCH + lmRow16;

    // K/V loader mapping
    const int kv_r = tid >> 2;
    const int kv_c = (tid & 3) * 16;
    const uint32_t dkBase = smem0 + AK_OFF + kv_r * APITCH + (tid & 3) * 32;
    const uint32_t dvBase = smem0 + AV_OFF + kv_r * APITCH + (tid & 3) * 32;

    const int ntiles = causal ? 2 * (blockIdx.x + 1) : ((Tk + 63) >> 6);

    // prologue: Q load + K/V tile 0
    {
        const int r = tid >> 1, hs = tid & 1;
        const __half* src = qbase + (size_t)(q0 + r) * q_rs + hs * 32;
        const uint32_t dst = smem0 + AQ_OFF + r * APITCH + hs * 64;
        #pragma unroll
        for (int j = 0; j < 4; j++) cp16(dst + j * 16, src + j * 8);
        asm volatile("cp.async.commit_group;");
    }
    {
        int sr = kv_r; if (sr >= Tk) sr = Tk - 1;
        const __half* ks = kbase + (size_t)sr * k_rs + kv_c;
        const __half* vs = vbase + (size_t)kv_r * vt_rs + kv_c;
        cp16(dkBase, ks);      cp16(dkBase + 16, ks + 8);
        cp16(dvBase, vs);      cp16(dvBase + 16, vs + 8);
        asm volatile("cp.async.commit_group;");
    }

    float mrun[2] = {-1e30f, -1e30f}, lrun[2] = {0.f, 0.f};
    float o[8][4];
    #pragma unroll
    for (int nf = 0; nf < 8; nf++)
        #pragma unroll
        for (int e = 0; e < 4; e++) o[nf][e] = 0.f;

    for (int kt = 0; kt < ntiles; kt++) {
        const int k0 = kt * 64;
        asm volatile("cp.async.wait_group 0;");
        __syncthreads();

        // prefetch tile kt+1 into buffer (kt+1)&1
        if (kt + 1 < ntiles) {
            const int k0n = k0 + 64;
            int sr = k0n + kv_r; if (sr >= Tk) sr = Tk - 1;
            const __half* ks = kbase + (size_t)sr * k_rs + kv_c;
            const __half* vs = vbase + (size_t)kv_r * vt_rs + k0n + kv_c;
            const uint32_t bo = ((kt + 1) & 1) * AKSTG;
            cp16(dkBase + bo, ks);      cp16(dkBase + bo + 16, ks + 8);
            cp16(dvBase + bo, vs);      cp16(dvBase + bo + 16, vs + 8);
            asm volatile("cp.async.commit_group;");
        }

        const uint32_t bo = (kt & 1) * AKSTG;

        // ---- S = Q K^T ----
        float sc[8][4];
        #pragma unroll
        for (int nf = 0; nf < 8; nf++)
            #pragma unroll
            for (int e = 0; e < 4; e++) sc[nf][e] = 0.f;

        #pragma unroll
        for (int ks = 0; ks < 4; ks++) {
            uint32_t a0, a1, a2, a3;
            ldsm_x4(a0, a1, a2, a3, qLm + ks * 32);
            #pragma unroll
            for (int p = 0; p < 4; p++) {
                uint32_t b00, b01, b10, b11;
                ldsm_x4(b00, b01, b10, b11, kLm + bo + p * (16 * APITCH) + ks * 32);
                mma_f16(sc[2 * p],     a0, a1, a2, a3, b00, b01);
                mma_f16(sc[2 * p + 1], a0, a1, a2, a3, b10, b11);
            }
        }

        // ---- scale + mask + online softmax ----
        const int qi0 = q0 + rw + g, qi1 = qi0 + 8;
        const int cmax0 = causal ? min(qi0, Tk - 1) : (Tk - 1);
        const int cmax1 = causal ? min(qi1, Tk - 1) : (Tk - 1);
        float m0 = -1e30f, m1 = -1e30f;
        #pragma unroll
        for (int nf = 0; nf < 8; nf++) {
            const int c0i = k0 + 8 * nf + 2 * tg;
            const int c1i = c0i + 1;
            sc[nf][0] = (c0i <= cmax0) ? sc[nf][0] * 0.125f : -1e30f;
            sc[nf][1] = (c1i <= cmax0) ? sc[nf][1] * 0.125f : -1e30f;
            sc[nf][2] = (c0i <= cmax1) ? sc[nf][2] * 0.125f : -1e30f;
            sc[nf][3] = (c1i <= cmax1) ? sc[nf][3] * 0.125f : -1e30f;
            m0 = fmaxf(m0, fmaxf(sc[nf][0], sc[nf][1]));
            m1 = fmaxf(m1, fmaxf(sc[nf][2], sc[nf][3]));
        }
        #pragma unroll
        for (int off = 1; off < 4; off <<= 1) {
            m0 = fmaxf(m0, __shfl_xor_sync(0xffffffffu, m0, off));
            m1 = fmaxf(m1, __shfl_xor_sync(0xffffffffu, m1, off));
        }
        const float mn0 = fmaxf(mrun[0], m0), mn1 = fmaxf(mrun[1], m1);
        const float corr0 = __expf(mrun[0] - mn0), corr1 = __expf(mrun[1] - mn1);
        mrun[0] = mn0; mrun[1] = mn1;

        float s0 = 0.f, s1 = 0.f;
        #pragma unroll
        for (int nf = 0; nf < 8; nf++) {
            float p00 = __expf(sc[nf][0] - mn0);
            float p01 = __expf(sc[nf][1] - mn0);
            float p10 = __expf(sc[nf][2] - mn1);
            float p11 = __expf(sc[nf][3] - mn1);
            s0 += p00 + p01; s1 += p10 + p11;
            P32[(rw + g)     * 36 + 4 * nf + tg] = pack_h2(p00, p01);
            P32[(rw + g + 8) * 36 + 4 * nf + tg] = pack_h2(p10, p11);
            o[nf][0] *= corr0; o[nf][1] *= corr0;
            o[nf][2] *= corr1; o[nf][3] *= corr1;
        }
        #pragma unroll
        for (int off = 1; off < 4; off <<= 1) {
            s0 += __shfl_xor_sync(0xffffffffu, s0, off);
            s1 += __shfl_xor_sync(0xffffffffu, s1, off);
        }
        lrun[0] = lrun[0] * corr0 + s0;
        lrun[1] = lrun[1] * corr1 + s1;
        __syncwarp();

        // ---- O += P V^T ----
        #pragma unroll
        for (int ks = 0; ks < 4; ks++) {
            uint32_t a0, a1, a2, a3;
            ldsm_x4(a0, a1, a2, a3, pLm + ks * 32);
            #pragma unroll
            for (int p = 0; p < 4; p++) {
                uint32_t b00, b01, b10, b11;
                ldsm_x4(b00, b01, b10, b11, vLm + bo + p * (16 * APITCH) + ks * 32);
                mma_f16(o[2 * p],     a0, a1, a2, a3, b00, b01);
                mma_f16(o[2 * p + 1], a0, a1, a2, a3, b10, b11);
            }
        }
    }

    const float inv0 = 1.f / lrun[0], inv1 = 1.f / lrun[1];
    const int t0 = q0 + rw + g, t1 = t0 + 8;
    __half* out0 = Op + ((size_t)b * Tq + t0) * o_rs + h * HDIM;
    __half* out1 = Op + ((size_t)b * Tq + t1) * o_rs + h * HDIM;
    #pragma unroll
    for (int nf = 0; nf < 8; nf++) {
        const int col = 8 * nf + 2 * tg;
        *(__half2*)&out0[col] = __floats2half2_rn(o[nf][0] * inv0, o[nf][1] * inv0);
        *(__half2*)&out1[col] = __floats2half2_rn(o[nf][2] * inv1, o[nf][3] * inv1);
    }
}

// ------------------------------- launch --------------------------------------
extern "C" void kernel_launch(void* const* d_in, const int* in_sizes, int n_in,
                              void* d_out, int out_size)
{
    const float* x            = (const float*)d_in[0];
    const float* encoder_x    = (const float*)d_in[1];
    const float* ln1_g        = (const float*)d_in[2];
    const float* ln1_b        = (const float*)d_in[3];
    const float* ln2_g        = (const float*)d_in[4];
    const float* ln2_b        = (const float*)d_in[5];
    const float* ln3_g        = (const float*)d_in[6];
    const float* ln3_b        = (const float*)d_in[7];
    const float* attn_w       = (const float*)d_in[8];
    const float* attn_b       = (const float*)d_in[9];
    const float* attn_proj_w  = (const float*)d_in[10];
    const float* attn_proj_b  = (const float*)d_in[11];
    const float* cross_w      = (const float*)d_in[12];
    const float* cross_b      = (const float*)d_in[13];
    const float* cross_proj_w = (const float*)d_in[14];
    const float* cross_proj_b = (const float*)d_in[15];
    const float* fc_w         = (const float*)d_in[16];
    const float* fc_b         = (const float*)d_in[17];
    const float* proj_w       = (const float*)d_in[18];
    const float* proj_b       = (const float*)d_in[19];

    __half *big, *hbuf, *obuf, *q2, *ekv, *enc, *vt, *vtc, *wt;
    float  *xbuf;
    cudaGetSymbolAddress((void**)&big,  g_big);
    cudaGetSymbolAddress((void**)&hbuf, g_h);
    cudaGetSymbolAddress((void**)&obuf, g_o);
    cudaGetSymbolAddress((void**)&xbuf, g_x);
    cudaGetSymbolAddress((void**)&q2,   g_q2);
    cudaGetSymbolAddress((void**)&ekv,  g_ekv);
    cudaGetSymbolAddress((void**)&enc,  g_enc);
    cudaGetSymbolAddress((void**)&vt,   g_vt);
    cudaGetSymbolAddress((void**)&vtc,  g_vtc);
    cudaGetSymbolAddress((void**)&wt,   g_wt);

    cudaFuncSetAttribute(attn_f16_kernel,
                         cudaFuncAttributeMaxDynamicSharedMemorySize,
                         ATTN_SMEM_BYTES);
    cudaFuncSetAttribute(gemm_f16_kernel,
                         cudaFuncAttributeMaxDynamicSharedMemorySize,
                         GEMM_SMEM_BYTES);

    const int M = MROWS;        // 8192
    dim3 blk(256);
    dim3 ga(TLEN / 128, NHEAD, BATCH);   // 8 x 12 x 8

    // 0a. convert+transpose all weights (fp32 [K][N] -> fp16 [N][K])
    wconv_kernel<<<dim3(2304/32, 768/32),  blk>>>(attn_w,       wt + OFF_ATTN,  768, 2304);
    wconv_kernel<<<dim3(768/32,  768/32),  blk>>>(attn_proj_w,  wt + OFF_APROJ, 768, 768);
    wconv_kernel<<<dim3(2304/32, 768/32),  blk>>>(cross_w,      wt + OFF_CROSS, 768, 2304);
    wconv_kernel<<<dim3(768/32,  768/32),  blk>>>(cross_proj_w, wt + OFF_CPROJ, 768, 768);
    wconv_kernel<<<dim3(3072/32, 768/32),  blk>>>(fc_w,         wt + OFF_FC,    768, 3072);
    wconv_kernel<<<dim3(768/32,  3072/32), blk>>>(proj_w,       wt + OFF_PROJ,  3072, 768);
    // 0b. encoder_x -> half
    f2h_kernel<<<(EROWS * D_MODEL + 255) / 256, blk>>>(encoder_x, enc, EROWS * D_MODEL);

    // 1. h = LN1(x)
    ln_kernel<<<M, blk>>>(x, ln1_g, ln1_b, hbuf);
    // 2. qkv = h @ attn_w + attn_b  (8192 x 2304, half out)
    gemm_f16_kernel<<<dim3(2304/128, M/128), blk, GEMM_SMEM_BYTES>>>(
        hbuf, 768, wt + OFF_ATTN, 768, attn_b, nullptr, big, 2304, M, 2304, 768, 0);
    // 2b. transpose self V -> vt [bh][d][t]
    vtrans_kernel<<<dim3(TLEN/32, HDIM/32, BATCH*NHEAD), blk>>>(
        big, vt, TLEN, 2304, TLEN, 1536);
    // 3. causal self-attention
    attn_f16_kernel<<<ga, blk, ATTN_SMEM_BYTES>>>(
        big, 2304, big + 768, 2304, vt, TLEN, obuf, 768, TLEN, TLEN, 1);
    // 4. x1 = x + o @ attn_proj_w + attn_proj_b  (float out)
    gemm_f16_kernel<<<dim3(768/128, M/128), blk, GEMM_SMEM_BYTES>>>(
        obuf, 768, wt + OFF_APROJ, 768, attn_proj_b, x, xbuf, 768, M, 768, 768, 1);
    // 5. h = LN2(x1)
    ln_kernel<<<M, blk>>>(xbuf, ln2_g, ln2_b, hbuf);
    // 6. q2 = h @ cross_w[:, :768] + cross_b[:768]  (half out)
    gemm_f16_kernel<<<dim3(768/128, M/128), blk, GEMM_SMEM_BYTES>>>(
        hbuf, 768, wt + OFF_CROSS, 768, cross_b, nullptr, q2, 768, M, 768, 768, 0);
    // 7. ekv = encoder_x @ cross_w[:, 768:] + cross_b[768:]  (2056 x 1536, half)
    gemm_f16_kernel<<<dim3(1536/128, (EROWS + 127)/128), blk, GEMM_SMEM_BYTES>>>(
        enc, 768, wt + OFF_CROSS + 768 * 768, 768, cross_b + 768, nullptr,
        ekv, 1536, EROWS, 1536, 768, 0);
    // 7b. transpose cross V -> vtc [bh][d][t_pad] (zero-padded to 320)
    vtrans_kernel<<<dim3(TPADC/32, HDIM/32, BATCH*NHEAD), blk>>>(
        ekv, vtc, SLEN, 1536, TPADC, 768);
    // 8. cross-attention (non-causal, Tk = 257)
    attn_f16_kernel<<<ga, blk, ATTN_SMEM_BYTES>>>(
        q2, 768, ekv, 1536, vtc, TPADC, obuf, 768, TLEN, SLEN, 0);
    // 9. x2 = x1 + o2 @ cross_proj_w + cross_proj_b  (float out, in-place resid)
    gemm_f16_kernel<<<dim3(768/128, M/128), blk, GEMM_SMEM_BYTES>>>(
        obuf, 768, wt + OFF_CPROJ, 768, cross_proj_b, xbuf, xbuf, 768, M, 768, 768, 1);
    // 10. h = LN3(x2)
    ln_kernel<<<M, blk>>>(xbuf, ln3_g, ln3_b, hbuf);
    // 11. fc = GELU(h @ fc_w + fc_b)  (8192 x 3072, half out)
    gemm_f16_kernel<<<dim3(3072/128, M/128), blk, GEMM_SMEM_BYTES>>>(
        hbuf, 768, wt + OFF_FC, 768, fc_b, nullptr, big, 3072, M, 3072, 768, 2);
    // 12. out = x2 + fc @ proj_w + proj_b  (float out)
    gemm_f16_kernel<<<dim3(768/128, M/128), blk, GEMM_SMEM_BYTES>>>(
        big, 3072, wt + OFF_PROJ, 3072, proj_b, xbuf, (float*)d_out, 768, M, 768, 3072, 1);
}